// round 12
// baseline (speedup 1.0000x reference)
#include <cuda_runtime.h>
#include <cuda_bf16.h>
#include <cuda_fp16.h>
#include <math.h>
#include <stdint.h>

// Problem constants
#define BB   512
#define SS   200
#define DD   128
#define NLAY 2
#define DH   256      // complex hidden (512 reals)
#define DFF  512
#define LPAD 256
#define PAD  56
#define MTOK (BB*LPAD)

typedef __half fp16;

// single dynamic-smem symbol shared by all kernels
extern __shared__ __align__(16) char dyn_smem[];

// ---------------- scratch (device globals) ------------------------------------
__device__ fp16 g_xh [MTOK * DD];
__device__ fp16 g_x2h[MTOK * DD];
__device__ fp16 g_hh [MTOK * 2*DH];
__device__ fp16 g_hfh[MTOK * DFF];
// packed weights for BOTH layers + lambda-power tables [li][grp 0..7][p-1][c 0..31]
__device__ fp16 g_Win[NLAY*2*DH*DD];
__device__ float g_bin[NLAY*2*DH];
__device__ fp16 g_Wout[NLAY*DD*2*DH];
__device__ fp16 g_w1[NLAY*DFF*DD];
__device__ fp16 g_w2[NLAY*DD*DFF];
__device__ float g_lamR[NLAY*8*128*32];
__device__ float g_lamI[NLAY*8*128*32];
// layer-2 tail (gathered, M=BB)
__device__ fp16 g_xgh[BB * DD];
__device__ fp16 g_sm1h[BB*DD];
__device__ fp16 g_sm2h[BB*DFF];
__device__ fp16 g_hgh[BB*2*DH];

// ---------------- helpers -------------------------------------------------------
__device__ __forceinline__ uint32_t smem_u32(const void* p) {
    uint32_t a;
    asm("{ .reg .u64 t; cvta.to.shared.u64 t, %1; cvt.u32.u64 %0, t; }" : "=r"(a) : "l"(p));
    return a;
}
__device__ __forceinline__ void cp_async16(uint32_t s, const void* g) {
    asm volatile("cp.async.cg.shared.global [%0], [%1], 16;" :: "r"(s), "l"(g));
}
__device__ __forceinline__ void ldsm4(uint32_t (&r)[4], uint32_t addr) {
    asm volatile("ldmatrix.sync.aligned.m8n8.x4.shared.b16 {%0,%1,%2,%3}, [%4];"
                 : "=r"(r[0]), "=r"(r[1]), "=r"(r[2]), "=r"(r[3]) : "r"(addr));
}
__device__ __forceinline__ void mma16816(float* c, const uint32_t* a, uint32_t b0, uint32_t b1) {
    asm volatile("mma.sync.aligned.m16n8k16.row.col.f32.f16.f16.f32 "
                 "{%0,%1,%2,%3}, {%4,%5,%6,%7}, {%8,%9}, {%0,%1,%2,%3};"
                 : "+f"(c[0]), "+f"(c[1]), "+f"(c[2]), "+f"(c[3])
                 : "r"(a[0]), "r"(a[1]), "r"(a[2]), "r"(a[3]), "r"(b0), "r"(b1));
}
__device__ __forceinline__ float block128_sum(float v, volatile float* sh) {
    #pragma unroll
    for (int o = 16; o > 0; o >>= 1) v += __shfl_xor_sync(0xffffffffu, v, o);
    __syncthreads();
    if ((threadIdx.x & 31) == 0) sh[threadIdx.x >> 5] = v;
    __syncthreads();
    return sh[0] + sh[1] + sh[2] + sh[3];
}
__device__ __forceinline__ void packh2(float a, float b, fp16* H, size_t idx) {
    *reinterpret_cast<__half2*>(H + idx) = __floats2half2_rn(a, b);
}

#define SM_FIX 1536
#define GP     144                // 64 fp16 = 128B + 16B pad (ldsm conflict-free)
#define GTILE  (128*GP)           // 18432
#define GSTAGE (2*GTILE)          // 36864 (A + B)
#define NSTAGE 3
#define GSM_TOT (SM_FIX + NSTAGE*GSTAGE)   // 112128 -> 2 CTAs/SM

// ---------------- embedding gather + LN + front-pad ----------------------------
__global__ void embed_kernel(const float* __restrict__ emb,
                             const float* __restrict__ g,
                             const float* __restrict__ bta,
                             const int*   __restrict__ seq,
                             fp16* __restrict__ xh) {
    __shared__ float sh[4];
    int b = blockIdx.y, t = blockIdx.x, tid = threadIdx.x;
    size_t o = ((size_t)b * LPAD + t) * DD + tid;
    float r;
    if (t < PAD) {
        r = 0.f;
    } else {
        int item = seq[b * SS + (t - PAD)];
        float v = emb[(size_t)item * DD + tid];
        float mu  = block128_sum(v, sh) * (1.f / DD);
        float d   = v - mu;
        float var = block128_sum(d * d, sh) * (1.f / DD);
        r = d * rsqrtf(var + 1e-5f) * g[tid] + bta[tid];
    }
    xh[o] = __float2half_rn(r);
}

// ---------------- lambda-power table (one layer per launch) ---------------------
__global__ void lam_kernel(const float* __restrict__ params_log, int li) {
    int idx = blockIdx.x * 256 + threadIdx.x;   // 0..32767
    int cg = idx >> 12, rem = idx & 4095;
    int p = (rem >> 5) + 1, c = rem & 31;
    int d = cg * 32 + c;
    float nu = expf(params_log[(li * 3 + 0) * DH + d]);
    float th = expf(params_log[(li * 3 + 1) * DH + d]);
    float mag = expf(-nu * (float)p);
    float sv, cv;
    sincosf(th * (float)p, &sv, &cv);
    g_lamR[li * 32768 + idx] = mag * cv;
    g_lamI[li * 32768 + idx] = mag * sv;
}

// ---------------- weight packing (one layer per launch, to fp16) ----------------
__global__ void pack_kernel(const float* __restrict__ in_wr, const float* __restrict__ in_wi,
                            const float* __restrict__ in_br, const float* __restrict__ in_bi,
                            const float* __restrict__ out_wr, const float* __restrict__ out_wi,
                            const float* __restrict__ w1, const float* __restrict__ w2,
                            const float* __restrict__ params_log, int li) {
    int idx = blockIdx.x * 256 + threadIdx.x;   // 0 .. 262143
    int mat = idx >> 16, r = idx & 65535;
    float w;
    fp16* Dst;
    if (mat == 0) {
        int n = r >> 7, k = r & 127;
        int d = n >> 1, s = n & 1;
        float gamma = expf(params_log[(li * 3 + 2) * DH + d]);
        w = (s ? in_wi[(size_t)li * DH * DD + d * DD + k]
               : in_wr[(size_t)li * DH * DD + d * DD + k]) * gamma;
        if (k == 0) {
            float bv = s ? in_bi[li * DH + d] : in_br[li * DH + d];
            g_bin[li * 2*DH + n] = bv * gamma;
        }
        Dst = g_Win + (size_t)li * 2*DH*DD;
    } else if (mat == 1) {
        int n = r >> 9, k = r & 511;
        int d = k >> 1, s = k & 1;
        w = s ? -out_wi[(size_t)li * DD * DH + n * DH + d]
              :  out_wr[(size_t)li * DD * DH + n * DH + d];
        Dst = g_Wout + (size_t)li * DD*2*DH;
    } else if (mat == 2) {
        w = w1[(size_t)li * DFF * DD + r];
        Dst = g_w1 + (size_t)li * DFF*DD;
    } else {
        w = w2[(size_t)li * DD * DFF + r];
        Dst = g_w2 + (size_t)li * DD*DFF;
    }
    Dst[r] = __float2half_rn(w);
}

// ---------------- gather last valid token --------------------------------------
__global__ void gather_kernel(const fp16* __restrict__ hh,
                              const fp16* __restrict__ xh, const int* __restrict__ slen,
                              fp16* __restrict__ hgh, fp16* __restrict__ xgh) {
    int b = blockIdx.x, tid = threadIdx.x;
    int t = PAD + slen[b] - 1;
    hgh[(size_t)b * 512 + tid] = hh[((size_t)b * LPAD + t) * 512 + tid];
    if (tid < DD) xgh[(size_t)b * DD + tid] = xh[((size_t)b * LPAD + t) * DD + tid];
}

// ================= fused in-projection GEMM + register tree scan =================
// Block = (cg 0..3, b): 256 tokens x 128 interleaved reals (64 complex channels).
// GEMM (fp16 single-pass, both K-chunks prefetched) -> fp32 smem buf ->
// register-resident masked tree scan -> single fp16 h store.
#define FA_TILE (256*GP)                 // 36864
#define FB_TILE (128*GP)                 // 18432
#define F_CH    (FA_TILE + FB_TILE)      // 55296 per chunk
#define F_BUF   (SM_FIX)                 // fp32 buf overlays tiles after GEMM
#define F_BND   (SM_FIX + 131072)        // float2 bnd[8][64] = 4096 B
#define F_SMEM  (SM_FIX + 131072 + 4096) // 136704

__global__ void __launch_bounds__(512, 1) fused_inproj_scan(
        const fp16* __restrict__ Ax, const fp16* __restrict__ Bw,
        const float* __restrict__ bias,
        fp16* __restrict__ hh,
        const int* __restrict__ seq, const int* __restrict__ slen, int li) {
    char* sm = dyn_smem;
    float* sBias = (float*)sm;             // [0,512)
    float* ms    = (float*)(sm + 512);     // [512,1536)
    float* buf   = (float*)(sm + F_BUF);   // 256*128 fp32 (overlays tiles)
    float2* bnd  = (float2*)(sm + F_BND);  // [8][64]
    uint32_t sb = smem_u32(sm);

    int tid = threadIdx.x, lane = tid & 31, wid = tid >> 5;
    int q = lane & 3, hrow = lane >> 2;
    int wm = wid & 7, wn = wid >> 3;
    int b = blockIdx.y, cg = blockIdx.x;   // cg 0..3
    int m0 = b * 256, n0 = cg * 128;

    // async prefetch of both K-chunks
    #pragma unroll
    for (int c = 0; c < 2; c++) {
        int kc = c * 64;
        uint32_t st = sb + SM_FIX + c * F_CH;
        #pragma unroll
        for (int t = 0; t < 4; t++) {           // A: 256 rows x 8 segs
            int idx = tid + t * 512;
            int row = idx >> 3, seg = idx & 7;
            cp_async16(st + row * GP + seg * 16,
                       Ax + (size_t)(m0 + row) * 128 + kc + seg * 8);
        }
        #pragma unroll
        for (int t = 0; t < 2; t++) {           // B: 128 rows x 8 segs
            int idx = tid + t * 512;
            int row = idx >> 3, seg = idx & 7;
            cp_async16(st + FA_TILE + row * GP + seg * 16,
                       Bw + (size_t)(n0 + row) * 128 + kc + seg * 8);
        }
        asm volatile("cp.async.commit_group;");
    }

    if (tid < 128) sBias[tid] = bias[n0 + tid];
    if (tid >= 256 && tid < 512) {
        int t = tid - 256;
        ms[t] = (t >= PAD && seq[b * SS + t - PAD] > 0) ? 1.f : 0.f;
    }
    int tb = PAD + slen[b] - 1;

    float acc[2][8][4];
    #pragma unroll
    for (int a1 = 0; a1 < 2; a1++)
        #pragma unroll
        for (int a2 = 0; a2 < 8; a2++)
            #pragma unroll
            for (int a3 = 0; a3 < 4; a3++) acc[a1][a2][a3] = 0.f;

    #pragma unroll
    for (int ch = 0; ch < 2; ch++) {
        if (ch == 0) asm volatile("cp.async.wait_group 1;");
        else         asm volatile("cp.async.wait_group 0;");
        __syncthreads();
        uint32_t st = sb + SM_FIX + ch * F_CH;
        uint32_t aA = st, aB = st + FA_TILE;
        #pragma unroll
        for (int ks = 0; ks < 4; ks++) {
            uint32_t ah[2][4];
            #pragma unroll
            for (int mt = 0; mt < 2; mt++) {
                uint32_t aoff = (uint32_t)((wm*32 + mt*16 + (lane & 15)) * GP + ks*32 + (lane >> 4) * 16);
                ldsm4(ah[mt], aA + aoff);
            }
            #pragma unroll
            for (int nb = 0; nb < 4; nb++) {
                uint32_t boff = (uint32_t)((wn*64 + nb*16 + (lane & 15)) * GP + ks*32 + (lane >> 4) * 16);
                uint32_t bh[4];
                ldsm4(bh, aB + boff);
                #pragma unroll
                for (int mt = 0; mt < 2; mt++) {
                    mma16816(acc[mt][2*nb],   ah[mt], bh[0], bh[2]);
                    mma16816(acc[mt][2*nb+1], ah[mt], bh[1], bh[3]);
                }
            }
        }
    }
    __syncthreads();

    // GEMM epilogue -> fp32 staging buf (overlays tiles)
    #pragma unroll
    for (int mt = 0; mt < 2; mt++) {
        int r0 = wm*32 + mt*16 + hrow;
        #pragma unroll
        for (int j = 0; j < 8; j++) {
            int col = wn*64 + j*8 + q*2;
            float b0 = sBias[col], b1 = sBias[col+1];
            *(float2*)&buf[r0*128 + col]     = make_float2(acc[mt][j][0] + b0, acc[mt][j][1] + b1);
            *(float2*)&buf[(r0+8)*128 + col] = make_float2(acc[mt][j][2] + b0, acc[mt][j][3] + b1);
        }
    }
    __syncthreads();

    // ---- register-resident masked tree scan ----
    // thread = (chunk tc 0..7, complex channel c 0..63)
    int c = tid & 63, tc = tid >> 6;
    int grp = (cg << 1) | (c >> 5), cc = c & 31;
    const float* lamR = g_lamR + ((size_t)li * 8 + grp) * 4096;
    const float* lamI = g_lamI + ((size_t)li * 8 + grp) * 4096;
    int t0 = tc * 32;
    bool live = (t0 <= tb);

    float2 h[32];
    #pragma unroll
    for (int j = 0; j < 32; j++)
        h[j] = *(float2*)&buf[(t0 + j) * 128 + 2 * c];

    // levels 1..5 entirely in registers
    #pragma unroll
    for (int lev = 1; lev <= 5; lev++) {
        int half = 1 << (lev - 1);
        #pragma unroll
        for (int s = 0; s < 32; s += (1 << lev)) {
            int cpos = t0 + s + half - 1;
            if (ms[cpos] != 0.f) {
                float2 src = h[s + half - 1];
                #pragma unroll
                for (int p = 1; p <= (1 << (lev - 1)); p++) {
                    int j = s + half - 1 + p;
                    float lr = lamR[(p - 1) * 32 + cc], li2 = lamI[(p - 1) * 32 + cc];
                    h[j].x += lr * src.x - li2 * src.y;
                    h[j].y += lr * src.y + li2 * src.x;
                }
            }
        }
    }

    // chunk-boundary exchange for levels 6..8
    bnd[tc * 64 + c] = h[31];
    __syncthreads();
    #pragma unroll
    for (int lev = 6; lev <= 8; lev++) {
        int l = 1 << lev, half = l >> 1;
        int blk = t0 >> lev;
        int cpos = blk * l + half - 1;
        if (live && t0 > cpos && ms[cpos] != 0.f) {
            float2 src = bnd[(cpos >> 5) * 64 + c];
            int p0 = t0 - cpos;
            #pragma unroll
            for (int j = 0; j < 32; j++) {
                int p = p0 + j;
                float lr = lamR[(p - 1) * 32 + cc], li2 = lamI[(p - 1) * 32 + cc];
                h[j].x += lr * src.x - li2 * src.y;
                h[j].y += lr * src.y + li2 * src.x;
            }
            bnd[tc * 64 + c] = h[31];
        }
        __syncthreads();
    }

    if (live) {
        size_t base = ((size_t)b * LPAD + t0) * 512 + cg * 128 + 2 * c;
        #pragma unroll
        for (int j = 0; j < 32; j++)
            *reinterpret_cast<__half2*>(hh + base + (size_t)j * 512) =
                __floats2half2_rn(h[j].x, h[j].y);
    } else if (t0 < 128) {
        // rows read by out-proj (lower tile) but dead: deterministic finite zeros
        size_t base = ((size_t)b * LPAD + t0) * 512 + cg * 128 + 2 * c;
        #pragma unroll
        for (int j = 0; j < 32; j++)
            *reinterpret_cast<__half2*>(hh + base + (size_t)j * 512) =
                __floats2half2_rn(0.f, 0.f);
    }
}

// ================= pipelined fp16 GEMM (BK=64, 3 stages, 2 CTAs/SM) =============
// EPI 1: bias+gelu. EPI 2: bias+residual(fp16)+LayerNorm (N==128).
__device__ __forceinline__ void gemm_load_chunk(
        uint32_t st, const fp16* A, const fp16* B,
        int m0, int n0, int kc, int K, int tid) {
    #pragma unroll
    for (int t = 0; t < 4; t++) {
        int idx = tid + t * 256;       // 0..1023
        int row = idx >> 3, seg = idx & 7;
        uint32_t so = row * GP + seg * 16;
        cp_async16(st + so,         A + (size_t)(m0 + row) * K + kc + seg * 8);
        cp_async16(st + GTILE + so, B + (size_t)(n0 + row) * K + kc + seg * 8);
    }
}

template<int EPI>
__global__ void __launch_bounds__(256, 2) hmma_gemm(
        const fp16* __restrict__ A, const fp16* __restrict__ B,
        const float* __restrict__ bias, const fp16* __restrict__ Res,
        const float* __restrict__ lng, const float* __restrict__ lnb,
        float* __restrict__ Cf, fp16* __restrict__ Ch,
        const int* __restrict__ lenp,
        int M, int N, int K) {
    // ragged early-exit: dead upper tile of a short batch
    if (lenp && (blockIdx.y & 1) && lenp[blockIdx.y >> 1] < 73) return;

    char* sm = dyn_smem;
    float* sBias = (float*)sm;
    float* sG    = sBias + 128;
    float* sB    = sG + 128;
    float* sred  = (float*)(sm + SM_FIX);   // overlay after mainloop
    uint32_t sb = smem_u32(sm);

    int tid = threadIdx.x, lane = tid & 31, wid = tid >> 5;
    int q = lane & 3, hrow = lane >> 2;
    int wm = wid & 3, wn = wid >> 2;
    int m0 = blockIdx.y * 128, n0 = blockIdx.x * 128;

    if (tid < 128) {
        sBias[tid] = bias[n0 + tid];
        if (EPI == 2) { sG[tid] = lng[n0 + tid]; sB[tid] = lnb[n0 + tid]; }
    }

    float acc[2][8][4];
    #pragma unroll
    for (int a1 = 0; a1 < 2; a1++)
        #pragma unroll
        for (int a2 = 0; a2 < 8; a2++)
            #pragma unroll
            for (int a3 = 0; a3 < 4; a3++) acc[a1][a2][a3] = 0.f;

    int nc = K >> 6;
    gemm_load_chunk(sb + SM_FIX, A, B, m0, n0, 0, K, tid);
    asm volatile("cp.async.commit_group;");
    if (nc > 1) gemm_load_chunk(sb + SM_FIX + GSTAGE, A, B, m0, n0, 64, K, tid);
    asm volatile("cp.async.commit_group;");

    for (int ch = 0; ch < nc; ch++) {
        if (ch + 2 < nc)
            gemm_load_chunk(sb + SM_FIX + ((ch + 2) % NSTAGE) * GSTAGE,
                            A, B, m0, n0, (ch + 2) << 6, K, tid);
        asm volatile("cp.async.commit_group;");
        asm volatile("cp.async.wait_group 2;");
        __syncthreads();
        uint32_t st = sb + SM_FIX + (ch % NSTAGE) * GSTAGE;
        uint32_t aA = st, aB = st + GTILE;
        #pragma unroll
        for (int ks = 0; ks < 4; ks++) {
            uint32_t ah[2][4];
            #pragma unroll
            for (int mt = 0; mt < 2; mt++) {
                uint32_t aoff = (uint32_t)((wm*32 + mt*16 + (lane & 15)) * GP + ks*32 + (lane >> 4) * 16);
                ldsm4(ah[mt], aA + aoff);
            }
            #pragma unroll
            for (int nb = 0; nb < 4; nb++) {
                uint32_t boff = (uint32_t)((wn*64 + nb*16 + (lane & 15)) * GP + ks*32 + (lane >> 4) * 16);
                uint32_t bh[4];
                ldsm4(bh, aB + boff);
                #pragma unroll
                for (int mt = 0; mt < 2; mt++) {
                    mma16816(acc[mt][2*nb],   ah[mt], bh[0], bh[2]);
                    mma16816(acc[mt][2*nb+1], ah[mt], bh[1], bh[3]);
                }
            }
        }
        __syncthreads();
    }

    // ---------------- epilogue ----------------
    #pragma unroll
    for (int mt = 0; mt < 2; mt++)
        #pragma unroll
        for (int j = 0; j < 8; j++) {
            int col = wn*64 + j*8 + q*2;
            float b0 = sBias[col], b1 = sBias[col+1];
            acc[mt][j][0] += b0; acc[mt][j][1] += b1;
            acc[mt][j][2] += b0; acc[mt][j][3] += b1;
        }
    if (EPI == 1) {
        #pragma unroll
        for (int mt = 0; mt < 2; mt++)
            #pragma unroll
            for (int j = 0; j < 8; j++)
                #pragma unroll
                for (int v = 0; v < 4; v++)
                    acc[mt][j][v] = 0.5f * acc[mt][j][v] *
                                    (1.f + erff(acc[mt][j][v] * 0.70710678118654752f));
    }
    if (EPI == 2) {
        float mu[2][2], rs[2][2];
        #pragma unroll
        for (int mt = 0; mt < 2; mt++) {
            int r0 = m0 + wm*32 + mt*16 + hrow;
            #pragma unroll
            for (int j = 0; j < 8; j++) {
                int col = wn*64 + j*8 + q*2;
                float2 ra = __half22float2(*(const __half2*)(Res + (size_t)r0 * 128 + col));
                float2 rb = __half22float2(*(const __half2*)(Res + (size_t)(r0+8) * 128 + col));
                acc[mt][j][0] += ra.x; acc[mt][j][1] += ra.y;
                acc[mt][j][2] += rb.x; acc[mt][j][3] += rb.y;
            }
        }
        float ssum[2][2] = {{0,0},{0,0}}, ssq[2][2] = {{0,0},{0,0}};
        #pragma unroll
        for (int mt = 0; mt < 2; mt++)
            #pragma unroll
            for (int j = 0; j < 8; j++)
                #pragma unroll
                for (int hh = 0; hh < 2; hh++) {
                    float v0 = acc[mt][j][2*hh], v1 = acc[mt][j][2*hh+1];
                    ssum[mt][hh] += v0 + v1;
                    ssq[mt][hh]  += v0*v0 + v1*v1;
                }
        #pragma unroll
        for (int mt = 0; mt < 2; mt++)
            #pragma unroll
            for (int hh = 0; hh < 2; hh++) {
                ssum[mt][hh] += __shfl_xor_sync(0xffffffffu, ssum[mt][hh], 1);
                ssum[mt][hh] += __shfl_xor_sync(0xffffffffu, ssum[mt][hh], 2);
                ssq[mt][hh]  += __shfl_xor_sync(0xffffffffu, ssq[mt][hh], 1);
                ssq[mt][hh]  += __shfl_xor_sync(0xffffffffu, ssq[mt][hh], 2);
            }
        if (q == 0) {
            #pragma unroll
            for (int mt = 0; mt < 2; mt++)
                #pragma unroll
                for (int hh = 0; hh < 2; hh++) {
                    int lr = wm*32 + mt*16 + hrow + hh*8;
                    sred[lr*2 + wn]       = ssum[mt][hh];
                    sred[256 + lr*2 + wn] = ssq[mt][hh];
                }
        }
        __syncthreads();
        #pragma unroll
        for (int mt = 0; mt < 2; mt++)
            #pragma unroll
            for (int hh = 0; hh < 2; hh++) {
                int lr = wm*32 + mt*16 + hrow + hh*8;
                float S  = sred[lr*2] + sred[lr*2 + 1];
                float S2 = sred[256 + lr*2] + sred[256 + lr*2 + 1];
                float m  = S * (1.f/128.f);
                float var = S2 * (1.f/128.f) - m * m;
                mu[mt][hh] = m;
                rs[mt][hh] = rsqrtf(var + 1e-5f);
            }
        #pragma unroll
        for (int mt = 0; mt < 2; mt++)
            #pragma unroll
            for (int j = 0; j < 8; j++) {
                int col = wn*64 + j*8 + q*2;
                float g0 = sG[col], g1 = sG[col+1], bb0 = sB[col], bb1 = sB[col+1];
                acc[mt][j][0] = (acc[mt][j][0] - mu[mt][0]) * rs[mt][0] * g0 + bb0;
                acc[mt][j][1] = (acc[mt][j][1] - mu[mt][0]) * rs[mt][0] * g1 + bb1;
                acc[mt][j][2] = (acc[mt][j][2] - mu[mt][1]) * rs[mt][1] * g0 + bb0;
                acc[mt][j][3] = (acc[mt][j][3] - mu[mt][1]) * rs[mt][1] * g1 + bb1;
            }
    }
    #pragma unroll
    for (int mt = 0; mt < 2; mt++) {
        int r0 = m0 + wm*32 + mt*16 + hrow;
        #pragma unroll
        for (int j = 0; j < 8; j++) {
            int col = n0 + wn*64 + j*8 + q*2;
            if (Cf) {
                *(float2*)(Cf + (size_t)r0 * N + col)     = make_float2(acc[mt][j][0], acc[mt][j][1]);
                *(float2*)(Cf + (size_t)(r0+8) * N + col) = make_float2(acc[mt][j][2], acc[mt][j][3]);
            }
            if (Ch) {
                packh2(acc[mt][j][0], acc[mt][j][1], Ch, (size_t)r0 * N + col);
                packh2(acc[mt][j][2], acc[mt][j][3], Ch, (size_t)(r0+8) * N + col);
            }
        }
    }
}

// ---------------- host driver ---------------------------------------------------
extern "C" void kernel_launch(void* const* d_in, const int* in_sizes, int n_in,
                              void* d_out, int out_size) {
    const float* token_emb  = (const float*)d_in[0];
    const float* emb_ln_g   = (const float*)d_in[1];
    const float* emb_ln_b   = (const float*)d_in[2];
    const float* params_log = (const float*)d_in[3];
    const float* in_wr      = (const float*)d_in[4];
    const float* in_wi      = (const float*)d_in[5];
    const float* in_br      = (const float*)d_in[6];
    const float* in_bi      = (const float*)d_in[7];
    const float* out_wr     = (const float*)d_in[8];
    const float* out_wi     = (const float*)d_in[9];
    const float* out_br     = (const float*)d_in[10];
    const float* lru_ln_g   = (const float*)d_in[12];
    const float* lru_ln_b   = (const float*)d_in[13];
    const float* w1         = (const float*)d_in[14];
    const float* b1         = (const float*)d_in[15];
    const float* w2         = (const float*)d_in[16];
    const float* b2         = (const float*)d_in[17];
    const float* ffn_ln_g   = (const float*)d_in[18];
    const float* ffn_ln_b   = (const float*)d_in[19];
    const int*   item_seq   = (const int*)d_in[20];
    const int*   item_len   = (const int*)d_in[21];
    float* out = (float*)d_out;

    float *pbin;
    fp16 *pxh, *px2h, *phh, *phfh, *pWin, *pWout, *pw1, *pw2;
    fp16 *psm1h, *psm2h, *phgh, *pxgh;
    cudaGetSymbolAddress((void**)&pxh,   g_xh);
    cudaGetSymbolAddress((void**)&px2h,  g_x2h);
    cudaGetSymbolAddress((void**)&phh,   g_hh);
    cudaGetSymbolAddress((void**)&phfh,  g_hfh);
    cudaGetSymbolAddress((void**)&pWin,  g_Win);
    cudaGetSymbolAddress((void**)&pbin,  g_bin);
    cudaGetSymbolAddress((void**)&pWout, g_Wout);
    cudaGetSymbolAddress((void**)&pw1,   g_w1);
    cudaGetSymbolAddress((void**)&pw2,   g_w2);
    cudaGetSymbolAddress((void**)&pxgh,  g_xgh);
    cudaGetSymbolAddress((void**)&psm1h, g_sm1h);
    cudaGetSymbolAddress((void**)&psm2h, g_sm2h);
    cudaGetSymbolAddress((void**)&phgh,  g_hgh);

    cudaFuncSetAttribute(hmma_gemm<1>, cudaFuncAttributeMaxDynamicSharedMemorySize, GSM_TOT);
    cudaFuncSetAttribute(hmma_gemm<2>, cudaFuncAttributeMaxDynamicSharedMemorySize, GSM_TOT);
    cudaFuncSetAttribute(fused_inproj_scan, cudaFuncAttributeMaxDynamicSharedMemorySize, F_SMEM);

    // weights + lambda tables for both layers, packed once up front
    for (int li = 0; li < NLAY; li++) {
        pack_kernel<<<1024, 256>>>(in_wr, in_wi, in_br, in_bi, out_wr, out_wi,
                                   w1, w2, params_log, li);
        lam_kernel<<<128, 256>>>(params_log, li);
    }
    embed_kernel<<<dim3(LPAD, BB), 128>>>(token_emb, emb_ln_g, emb_ln_b, item_seq, pxh);

    for (int li = 0; li < NLAY; li++) {
        // fused in-projection GEMM + masked LRU tree scan
        fused_inproj_scan<<<dim3(4, BB), 512, F_SMEM>>>(
            pxh, pWin + (size_t)li * 2*DH*DD, pbin + li * 2*DH,
            phh, item_seq, item_len, li);

        if (li == 0) {
            hmma_gemm<2><<<dim3(1, MTOK/128), 256, GSM_TOT>>>(
                phh, pWout + (size_t)li * DD*2*DH, out_br + li*DD, pxh,
                lru_ln_g + li*DD, lru_ln_b + li*DD,
                nullptr, px2h, item_len, MTOK, 128, 512);
            hmma_gemm<1><<<dim3(4, MTOK/128), 256, GSM_TOT>>>(
                px2h, pw1 + (size_t)li * DFF*DD, b1 + li*DFF, nullptr, nullptr, nullptr,
                nullptr, phfh, item_len, MTOK, 512, 128);
            hmma_gemm<2><<<dim3(1, MTOK/128), 256, GSM_TOT>>>(
                phfh, pw2 + (size_t)li * DD*DFF, b2 + li*DD, px2h,
                ffn_ln_g + li*DD, ffn_ln_b + li*DD,
                nullptr, pxh, item_len, MTOK, 128, 512);
        } else {
            gather_kernel<<<BB, 512>>>(phh, pxh, item_len, phgh, pxgh);
            hmma_gemm<2><<<dim3(1, BB/128), 256, GSM_TOT>>>(
                phgh, pWout + (size_t)li * DD*2*DH, out_br + li*DD, pxgh,
                lru_ln_g + li*DD, lru_ln_b + li*DD,
                nullptr, psm1h, nullptr, BB, 128, 512);
            hmma_gemm<1><<<dim3(4, BB/128), 256, GSM_TOT>>>(
                psm1h, pw1 + (size_t)li * DFF*DD, b1 + li*DFF, nullptr, nullptr, nullptr,
                nullptr, psm2h, nullptr, BB, 512, 128);
            hmma_gemm<2><<<dim3(1, BB/128), 256, GSM_TOT>>>(
                psm2h, pw2 + (size_t)li * DD*DFF, b2 + li*DD, psm1h,
                ffn_ln_g + li*DD, ffn_ln_b + li*DD,
                out, nullptr, nullptr, BB, 128, 512);
        }
    }
}

// round 13
// speedup vs baseline: 1.1138x; 1.1138x over previous
#include <cuda_runtime.h>
#include <cuda_bf16.h>
#include <cuda_fp16.h>
#include <math.h>
#include <stdint.h>

// Problem constants
#define BB   512
#define SS   200
#define DD   128
#define NLAY 2
#define DH   256      // complex hidden (512 reals)
#define DFF  512
#define LPAD 256
#define PAD  56
#define MTOK (BB*LPAD)

typedef __half fp16;

// single dynamic-smem symbol shared by all kernels
extern __shared__ __align__(16) char dyn_smem[];

// ---------------- scratch (device globals) ------------------------------------
__device__ fp16 g_xh [MTOK * DD];
__device__ fp16 g_x2h[MTOK * DD];
__device__ fp16 g_hh [MTOK * 2*DH];
__device__ fp16 g_hfh[MTOK * DFF];
// packed weights for BOTH layers + lambda tables [li][grp 0..7][p-1][c 0..31]
__device__ fp16 g_Win[NLAY*2*DH*DD];
__device__ float g_bin[NLAY*2*DH];
__device__ fp16 g_Wout[NLAY*DD*2*DH];
__device__ fp16 g_w1[NLAY*DFF*DD];
__device__ fp16 g_w2[NLAY*DD*DFF];
__device__ float g_lamR[NLAY*8*128*32];
__device__ float g_lamI[NLAY*8*128*32];
// layer-2 tail (gathered, M=BB)
__device__ fp16 g_xgh[BB * DD];
__device__ fp16 g_sm1h[BB*DD];
__device__ fp16 g_sm2h[BB*DFF];
__device__ fp16 g_hgh[BB*2*DH];

// ---------------- helpers -------------------------------------------------------
__device__ __forceinline__ uint32_t smem_u32(const void* p) {
    uint32_t a;
    asm("{ .reg .u64 t; cvta.to.shared.u64 t, %1; cvt.u32.u64 %0, t; }" : "=r"(a) : "l"(p));
    return a;
}
__device__ __forceinline__ void cp_async16(uint32_t s, const void* g) {
    asm volatile("cp.async.cg.shared.global [%0], [%1], 16;" :: "r"(s), "l"(g));
}
__device__ __forceinline__ void ldsm4(uint32_t (&r)[4], uint32_t addr) {
    asm volatile("ldmatrix.sync.aligned.m8n8.x4.shared.b16 {%0,%1,%2,%3}, [%4];"
                 : "=r"(r[0]), "=r"(r[1]), "=r"(r[2]), "=r"(r[3]) : "r"(addr));
}
__device__ __forceinline__ void mma16816(float* c, const uint32_t* a, uint32_t b0, uint32_t b1) {
    asm volatile("mma.sync.aligned.m16n8k16.row.col.f32.f16.f16.f32 "
                 "{%0,%1,%2,%3}, {%4,%5,%6,%7}, {%8,%9}, {%0,%1,%2,%3};"
                 : "+f"(c[0]), "+f"(c[1]), "+f"(c[2]), "+f"(c[3])
                 : "r"(a[0]), "r"(a[1]), "r"(a[2]), "r"(a[3]), "r"(b0), "r"(b1));
}
__device__ __forceinline__ void packh2(float a, float b, fp16* H, size_t idx) {
    *reinterpret_cast<__half2*>(H + idx) = __floats2half2_rn(a, b);
}

#define SM_FIX 1536
#define GP     144                // 64 fp16 = 128B + 16B pad (ldsm conflict-free)
#define GTILE  (128*GP)           // 18432
#define GSTAGE (2*GTILE)          // 36864 (A + B)
#define NSTAGE 3
#define GSM_TOT (SM_FIX + NSTAGE*GSTAGE)   // 112128 -> 2 CTAs/SM

// ---------------- embedding gather + LN + front-pad (warp per token) ------------
__global__ void embed_kernel(const float* __restrict__ emb,
                             const float* __restrict__ g,
                             const float* __restrict__ bta,
                             const int*   __restrict__ seq,
                             fp16* __restrict__ xh) {
    int gidx = blockIdx.x * 8 + (threadIdx.x >> 5);   // token 0..131071
    int lane = threadIdx.x & 31;
    int b = gidx >> 8, t = gidx & 255;
    size_t o = (size_t)gidx * DD + lane * 4;          // element index
    if (t < PAD) {
        *reinterpret_cast<uint2*>(&((fp16*)xh)[o]) = make_uint2(0u, 0u);
        return;
    }
    int item = seq[b * SS + (t - PAD)];
    float4 v = *reinterpret_cast<const float4*>(emb + (size_t)item * DD + lane * 4);
    float s = v.x + v.y + v.z + v.w;
    #pragma unroll
    for (int off = 16; off > 0; off >>= 1) s += __shfl_xor_sync(0xffffffffu, s, off);
    float mu = s * (1.f / DD);
    float dx = v.x - mu, dy = v.y - mu, dz = v.z - mu, dw = v.w - mu;
    float q = dx*dx + dy*dy + dz*dz + dw*dw;
    #pragma unroll
    for (int off = 16; off > 0; off >>= 1) q += __shfl_xor_sync(0xffffffffu, q, off);
    float rs = rsqrtf(q * (1.f / DD) + 1e-5f);
    float4 gg = *reinterpret_cast<const float4*>(g + lane * 4);
    float4 bb = *reinterpret_cast<const float4*>(bta + lane * 4);
    __half2 h01 = __floats2half2_rn(dx * rs * gg.x + bb.x, dy * rs * gg.y + bb.y);
    __half2 h23 = __floats2half2_rn(dz * rs * gg.z + bb.z, dw * rs * gg.w + bb.w);
    uint2 pk;
    pk.x = *reinterpret_cast<uint32_t*>(&h01);
    pk.y = *reinterpret_cast<uint32_t*>(&h23);
    *reinterpret_cast<uint2*>(&xh[o]) = pk;
}

// ---------------- lambda-power table (one layer per launch) ---------------------
__global__ void lam_kernel(const float* __restrict__ params_log, int li) {
    int idx = blockIdx.x * 256 + threadIdx.x;   // 0..32767
    int cg = idx >> 12, rem = idx & 4095;
    int p = (rem >> 5) + 1, c = rem & 31;
    int d = cg * 32 + c;
    float nu = expf(params_log[(li * 3 + 0) * DH + d]);
    float th = expf(params_log[(li * 3 + 1) * DH + d]);
    float mag = expf(-nu * (float)p);
    float sv, cv;
    sincosf(th * (float)p, &sv, &cv);
    g_lamR[li * 32768 + idx] = mag * cv;
    g_lamI[li * 32768 + idx] = mag * sv;
}

// ---------------- weight packing (one layer per launch, to fp16) ----------------
__global__ void pack_kernel(const float* __restrict__ in_wr, const float* __restrict__ in_wi,
                            const float* __restrict__ in_br, const float* __restrict__ in_bi,
                            const float* __restrict__ out_wr, const float* __restrict__ out_wi,
                            const float* __restrict__ w1, const float* __restrict__ w2,
                            const float* __restrict__ params_log, int li) {
    int idx = blockIdx.x * 256 + threadIdx.x;   // 0 .. 262143
    int mat = idx >> 16, r = idx & 65535;
    float w;
    fp16* Dst;
    if (mat == 0) {
        int n = r >> 7, k = r & 127;
        int d = n >> 1, s = n & 1;
        float gamma = expf(params_log[(li * 3 + 2) * DH + d]);
        w = (s ? in_wi[(size_t)li * DH * DD + d * DD + k]
               : in_wr[(size_t)li * DH * DD + d * DD + k]) * gamma;
        if (k == 0) {
            float bv = s ? in_bi[li * DH + d] : in_br[li * DH + d];
            g_bin[li * 2*DH + n] = bv * gamma;
        }
        Dst = g_Win + (size_t)li * 2*DH*DD;
    } else if (mat == 1) {
        int n = r >> 9, k = r & 511;
        int d = k >> 1, s = k & 1;
        w = s ? -out_wi[(size_t)li * DD * DH + n * DH + d]
              :  out_wr[(size_t)li * DD * DH + n * DH + d];
        Dst = g_Wout + (size_t)li * DD*2*DH;
    } else if (mat == 2) {
        w = w1[(size_t)li * DFF * DD + r];
        Dst = g_w1 + (size_t)li * DFF*DD;
    } else {
        w = w2[(size_t)li * DD * DFF + r];
        Dst = g_w2 + (size_t)li * DD*DFF;
    }
    Dst[r] = __float2half_rn(w);
}

// ---------------- gather last valid token --------------------------------------
__global__ void gather_kernel(const fp16* __restrict__ hh,
                              const fp16* __restrict__ xh, const int* __restrict__ slen,
                              fp16* __restrict__ hgh, fp16* __restrict__ xgh) {
    int b = blockIdx.x, tid = threadIdx.x;
    int t = PAD + slen[b] - 1;
    hgh[(size_t)b * 512 + tid] = hh[((size_t)b * LPAD + t) * 512 + tid];
    if (tid < DD) xgh[(size_t)b * DD + tid] = xh[((size_t)b * LPAD + t) * DD + tid];
}

// ================= register-resident masked LRU tree scan =======================
// Block = (cg, b): 32 complex channels x 256 timesteps, in place on fp16 h.
__global__ void __launch_bounds__(256) scan_kernel(fp16* __restrict__ hh,
                                                   const int* __restrict__ seq,
                                                   const int* __restrict__ slen, int li) {
    __shared__ float ms[LPAD];
    __shared__ float2 bnd[8][32];
    int b = blockIdx.y, cg = blockIdx.x;     // cg 0..7
    int tid = threadIdx.x;
    int c = tid & 31, tc = tid >> 5;         // tc 0..7
    const float* lamR = g_lamR + ((size_t)li * 8 + cg) * 4096;
    const float* lamI = g_lamI + ((size_t)li * 8 + cg) * 4096;

    ms[tid] = (tid >= PAD && seq[b * SS + tid - PAD] > 0) ? 1.f : 0.f;
    int tb = PAD + slen[b] - 1;              // last live position

    int t0 = tc * 32;
    bool live = (t0 <= tb);
    size_t base = ((size_t)b * LPAD + t0) * 512 + cg * 64 + 2 * c;
    float2 h[32];
    if (live) {
        #pragma unroll
        for (int j = 0; j < 32; j++)
            h[j] = __half22float2(*reinterpret_cast<const __half2*>(hh + base + (size_t)j * 512));
    } else {
        #pragma unroll
        for (int j = 0; j < 32; j++) h[j] = make_float2(0.f, 0.f);
    }
    __syncthreads();

    // levels 1..5 entirely in registers
    #pragma unroll
    for (int lev = 1; lev <= 5; lev++) {
        int half = 1 << (lev - 1);
        #pragma unroll
        for (int s = 0; s < 32; s += (1 << lev)) {
            int cpos = t0 + s + half - 1;
            if (ms[cpos] != 0.f) {
                float2 src = h[s + half - 1];
                #pragma unroll
                for (int p = 1; p <= (1 << (lev - 1)); p++) {
                    int j = s + half - 1 + p;
                    float lr = lamR[(p - 1) * 32 + c], liw = lamI[(p - 1) * 32 + c];
                    h[j].x += lr * src.x - liw * src.y;
                    h[j].y += lr * src.y + liw * src.x;
                }
            }
        }
    }

    // chunk-boundary exchange for levels 6..8
    bnd[tc][c] = h[31];
    __syncthreads();
    #pragma unroll
    for (int lev = 6; lev <= 8; lev++) {
        int l = 1 << lev, half = l >> 1;
        int blk = t0 >> lev;
        int cpos = blk * l + half - 1;
        if (live && t0 > cpos && ms[cpos] != 0.f) {
            float2 src = bnd[cpos >> 5][c];
            int p0 = t0 - cpos;
            #pragma unroll
            for (int j = 0; j < 32; j++) {
                int p = p0 + j;
                float lr = lamR[(p - 1) * 32 + c], liw = lamI[(p - 1) * 32 + c];
                h[j].x += lr * src.x - liw * src.y;
                h[j].y += lr * src.y + liw * src.x;
            }
            bnd[tc][c] = h[31];
        }
        __syncthreads();
    }

    if (live) {
        #pragma unroll
        for (int j = 0; j < 32; j++)
            *reinterpret_cast<__half2*>(hh + base + (size_t)j * 512) =
                __floats2half2_rn(h[j].x, h[j].y);
    }
}

// ================= pipelined fp16 GEMM (BK=64, 3 stages, 2 CTAs/SM) =============
// EPI 0: bias. EPI 1: bias+gelu. EPI 2: bias+residual(fp16)+LayerNorm (N==128).
// Single barrier per chunk: next-chunk loads issued AFTER the MMA phase (target
// stage (ch+2)%3 is not read by anyone at that point).
__device__ __forceinline__ void gemm_load_chunk(
        uint32_t st, const fp16* A, const fp16* B,
        int m0, int n0, int kc, int K, int tid) {
    #pragma unroll
    for (int t = 0; t < 4; t++) {
        int idx = tid + t * 256;       // 0..1023
        int row = idx >> 3, seg = idx & 7;
        uint32_t so = row * GP + seg * 16;
        cp_async16(st + so,         A + (size_t)(m0 + row) * K + kc + seg * 8);
        cp_async16(st + GTILE + so, B + (size_t)(n0 + row) * K + kc + seg * 8);
    }
}

template<int EPI>
__global__ void __launch_bounds__(256, 2) hmma_gemm(
        const fp16* __restrict__ A, const fp16* __restrict__ B,
        const float* __restrict__ bias, const fp16* __restrict__ Res,
        const float* __restrict__ lng, const float* __restrict__ lnb,
        float* __restrict__ Cf, fp16* __restrict__ Ch,
        const int* __restrict__ lenp,
        int M, int N, int K) {
    // ragged early-exit: dead upper tile of a short batch
    if (lenp && (blockIdx.y & 1) && lenp[blockIdx.y >> 1] < 73) return;

    char* sm = dyn_smem;
    float* sBias = (float*)sm;
    float* sG    = sBias + 128;
    float* sB    = sG + 128;
    float* sred  = (float*)(sm + SM_FIX);   // overlay after mainloop
    uint32_t sb = smem_u32(sm);

    int tid = threadIdx.x, lane = tid & 31, wid = tid >> 5;
    int q = lane & 3, hrow = lane >> 2;
    int wm = wid & 3, wn = wid >> 2;
    int m0 = blockIdx.y * 128, n0 = blockIdx.x * 128;

    if (tid < 128) {
        sBias[tid] = bias[n0 + tid];
        if (EPI == 2) { sG[tid] = lng[n0 + tid]; sB[tid] = lnb[n0 + tid]; }
    }

    float acc[2][8][4];
    #pragma unroll
    for (int a1 = 0; a1 < 2; a1++)
        #pragma unroll
        for (int a2 = 0; a2 < 8; a2++)
            #pragma unroll
            for (int a3 = 0; a3 < 4; a3++) acc[a1][a2][a3] = 0.f;

    int nc = K >> 6;
    gemm_load_chunk(sb + SM_FIX, A, B, m0, n0, 0, K, tid);
    asm volatile("cp.async.commit_group;");
    if (nc > 1) gemm_load_chunk(sb + SM_FIX + GSTAGE, A, B, m0, n0, 64, K, tid);
    asm volatile("cp.async.commit_group;");

    for (int ch = 0; ch < nc; ch++) {
        asm volatile("cp.async.wait_group 1;");
        __syncthreads();
        uint32_t st = sb + SM_FIX + (ch % NSTAGE) * GSTAGE;
        uint32_t aA = st, aB = st + GTILE;
        #pragma unroll
        for (int ks = 0; ks < 4; ks++) {
            uint32_t ah[2][4];
            #pragma unroll
            for (int mt = 0; mt < 2; mt++) {
                uint32_t aoff = (uint32_t)((wm*32 + mt*16 + (lane & 15)) * GP + ks*32 + (lane >> 4) * 16);
                ldsm4(ah[mt], aA + aoff);
            }
            #pragma unroll
            for (int nb = 0; nb < 4; nb++) {
                uint32_t boff = (uint32_t)((wn*64 + nb*16 + (lane & 15)) * GP + ks*32 + (lane >> 4) * 16);
                uint32_t bh[4];
                ldsm4(bh, aB + boff);
                #pragma unroll
                for (int mt = 0; mt < 2; mt++) {
                    mma16816(acc[mt][2*nb],   ah[mt], bh[0], bh[2]);
                    mma16816(acc[mt][2*nb+1], ah[mt], bh[1], bh[3]);
                }
            }
        }
        // issue next prefetch after MMA; stage (ch+2)%3 is idle here
        if (ch + 2 < nc)
            gemm_load_chunk(sb + SM_FIX + ((ch + 2) % NSTAGE) * GSTAGE,
                            A, B, m0, n0, (ch + 2) << 6, K, tid);
        asm volatile("cp.async.commit_group;");
    }
    __syncthreads();

    // ---------------- epilogue ----------------
    #pragma unroll
    for (int mt = 0; mt < 2; mt++)
        #pragma unroll
        for (int j = 0; j < 8; j++) {
            int col = wn*64 + j*8 + q*2;
            float b0 = sBias[col], b1 = sBias[col+1];
            acc[mt][j][0] += b0; acc[mt][j][1] += b1;
            acc[mt][j][2] += b0; acc[mt][j][3] += b1;
        }
    if (EPI == 1) {
        #pragma unroll
        for (int mt = 0; mt < 2; mt++)
            #pragma unroll
            for (int j = 0; j < 8; j++)
                #pragma unroll
                for (int v = 0; v < 4; v++)
                    acc[mt][j][v] = 0.5f * acc[mt][j][v] *
                                    (1.f + erff(acc[mt][j][v] * 0.70710678118654752f));
    }
    if (EPI == 2) {
        float mu[2][2], rs[2][2];
        #pragma unroll
        for (int mt = 0; mt < 2; mt++) {
            int r0 = m0 + wm*32 + mt*16 + hrow;
            #pragma unroll
            for (int j = 0; j < 8; j++) {
                int col = wn*64 + j*8 + q*2;
                float2 ra = __half22float2(*(const __half2*)(Res + (size_t)r0 * 128 + col));
                float2 rb = __half22float2(*(const __half2*)(Res + (size_t)(r0+8) * 128 + col));
                acc[mt][j][0] += ra.x; acc[mt][j][1] += ra.y;
                acc[mt][j][2] += rb.x; acc[mt][j][3] += rb.y;
            }
        }
        float ssum[2][2] = {{0,0},{0,0}}, ssq[2][2] = {{0,0},{0,0}};
        #pragma unroll
        for (int mt = 0; mt < 2; mt++)
            #pragma unroll
            for (int j = 0; j < 8; j++)
                #pragma unroll
                for (int hh = 0; hh < 2; hh++) {
                    float v0 = acc[mt][j][2*hh], v1 = acc[mt][j][2*hh+1];
                    ssum[mt][hh] += v0 + v1;
                    ssq[mt][hh]  += v0*v0 + v1*v1;
                }
        #pragma unroll
        for (int mt = 0; mt < 2; mt++)
            #pragma unroll
            for (int hh = 0; hh < 2; hh++) {
                ssum[mt][hh] += __shfl_xor_sync(0xffffffffu, ssum[mt][hh], 1);
                ssum[mt][hh] += __shfl_xor_sync(0xffffffffu, ssum[mt][hh], 2);
                ssq[mt][hh]  += __shfl_xor_sync(0xffffffffu, ssq[mt][hh], 1);
                ssq[mt][hh]  += __shfl_xor_sync(0xffffffffu, ssq[mt][hh], 2);
            }
        if (q == 0) {
            #pragma unroll
            for (int mt = 0; mt < 2; mt++)
                #pragma unroll
                for (int hh = 0; hh < 2; hh++) {
                    int lr = wm*32 + mt*16 + hrow + hh*8;
                    sred[lr*2 + wn]       = ssum[mt][hh];
                    sred[256 + lr*2 + wn] = ssq[mt][hh];
                }
        }
        __syncthreads();
        #pragma unroll
        for (int mt = 0; mt < 2; mt++)
            #pragma unroll
            for (int hh = 0; hh < 2; hh++) {
                int lr = wm*32 + mt*16 + hrow + hh*8;
                float S  = sred[lr*2] + sred[lr*2 + 1];
                float S2 = sred[256 + lr*2] + sred[256 + lr*2 + 1];
                float m  = S * (1.f/128.f);
                float var = S2 * (1.f/128.f) - m * m;
                mu[mt][hh] = m;
                rs[mt][hh] = rsqrtf(var + 1e-5f);
            }
        #pragma unroll
        for (int mt = 0; mt < 2; mt++)
            #pragma unroll
            for (int j = 0; j < 8; j++) {
                int col = wn*64 + j*8 + q*2;
                float g0 = sG[col], g1 = sG[col+1], bb0 = sB[col], bb1 = sB[col+1];
                acc[mt][j][0] = (acc[mt][j][0] - mu[mt][0]) * rs[mt][0] * g0 + bb0;
                acc[mt][j][1] = (acc[mt][j][1] - mu[mt][0]) * rs[mt][0] * g1 + bb1;
                acc[mt][j][2] = (acc[mt][j][2] - mu[mt][1]) * rs[mt][1] * g0 + bb0;
                acc[mt][j][3] = (acc[mt][j][3] - mu[mt][1]) * rs[mt][1] * g1 + bb1;
            }
    }
    #pragma unroll
    for (int mt = 0; mt < 2; mt++) {
        int r0 = m0 + wm*32 + mt*16 + hrow;
        #pragma unroll
        for (int j = 0; j < 8; j++) {
            int col = n0 + wn*64 + j*8 + q*2;
            if (Cf) {
                *(float2*)(Cf + (size_t)r0 * N + col)     = make_float2(acc[mt][j][0], acc[mt][j][1]);
                *(float2*)(Cf + (size_t)(r0+8) * N + col) = make_float2(acc[mt][j][2], acc[mt][j][3]);
            }
            if (Ch) {
                packh2(acc[mt][j][0], acc[mt][j][1], Ch, (size_t)r0 * N + col);
                packh2(acc[mt][j][2], acc[mt][j][3], Ch, (size_t)(r0+8) * N + col);
            }
        }
    }
}

// ---------------- host driver ---------------------------------------------------
extern "C" void kernel_launch(void* const* d_in, const int* in_sizes, int n_in,
                              void* d_out, int out_size) {
    const float* token_emb  = (const float*)d_in[0];
    const float* emb_ln_g   = (const float*)d_in[1];
    const float* emb_ln_b   = (const float*)d_in[2];
    const float* params_log = (const float*)d_in[3];
    const float* in_wr      = (const float*)d_in[4];
    const float* in_wi      = (const float*)d_in[5];
    const float* in_br      = (const float*)d_in[6];
    const float* in_bi      = (const float*)d_in[7];
    const float* out_wr     = (const float*)d_in[8];
    const float* out_wi     = (const float*)d_in[9];
    const float* out_br     = (const float*)d_in[10];
    const float* lru_ln_g   = (const float*)d_in[12];
    const float* lru_ln_b   = (const float*)d_in[13];
    const float* w1         = (const float*)d_in[14];
    const float* b1         = (const float*)d_in[15];
    const float* w2         = (const float*)d_in[16];
    const float* b2         = (const float*)d_in[17];
    const float* ffn_ln_g   = (const float*)d_in[18];
    const float* ffn_ln_b   = (const float*)d_in[19];
    const int*   item_seq   = (const int*)d_in[20];
    const int*   item_len   = (const int*)d_in[21];
    float* out = (float*)d_out;

    float *pbin;
    fp16 *pxh, *px2h, *phh, *phfh, *pWin, *pWout, *pw1, *pw2;
    fp16 *psm1h, *psm2h, *phgh, *pxgh;
    cudaGetSymbolAddress((void**)&pxh,   g_xh);
    cudaGetSymbolAddress((void**)&px2h,  g_x2h);
    cudaGetSymbolAddress((void**)&phh,   g_hh);
    cudaGetSymbolAddress((void**)&phfh,  g_hfh);
    cudaGetSymbolAddress((void**)&pWin,  g_Win);
    cudaGetSymbolAddress((void**)&pbin,  g_bin);
    cudaGetSymbolAddress((void**)&pWout, g_Wout);
    cudaGetSymbolAddress((void**)&pw1,   g_w1);
    cudaGetSymbolAddress((void**)&pw2,   g_w2);
    cudaGetSymbolAddress((void**)&pxgh,  g_xgh);
    cudaGetSymbolAddress((void**)&psm1h, g_sm1h);
    cudaGetSymbolAddress((void**)&psm2h, g_sm2h);
    cudaGetSymbolAddress((void**)&phgh,  g_hgh);

    cudaFuncSetAttribute(hmma_gemm<0>, cudaFuncAttributeMaxDynamicSharedMemorySize, GSM_TOT);
    cudaFuncSetAttribute(hmma_gemm<1>, cudaFuncAttributeMaxDynamicSharedMemorySize, GSM_TOT);
    cudaFuncSetAttribute(hmma_gemm<2>, cudaFuncAttributeMaxDynamicSharedMemorySize, GSM_TOT);

    // pack weights + lambda tables for both layers up front
    for (int li = 0; li < NLAY; li++) {
        pack_kernel<<<1024, 256>>>(in_wr, in_wi, in_br, in_bi, out_wr, out_wi,
                                   w1, w2, params_log, li);
        lam_kernel<<<128, 256>>>(params_log, li);
    }
    embed_kernel<<<MTOK/8, 256>>>(token_emb, emb_ln_g, emb_ln_b, item_seq, pxh);

    for (int li = 0; li < NLAY; li++) {
        // in-projection (bias folded, fp16 out, interleaved complex columns)
        hmma_gemm<0><<<dim3(4, MTOK/128), 256, GSM_TOT>>>(
            pxh, pWin + (size_t)li * 2*DH*DD, pbin + li * 2*DH, nullptr, nullptr, nullptr,
            nullptr, phh, item_len, MTOK, 512, 128);
        // masked LRU tree scan, register-resident, in place
        scan_kernel<<<dim3(8, BB), 256>>>(phh, item_seq, item_len, li);

        if (li == 0) {
            hmma_gemm<2><<<dim3(1, MTOK/128), 256, GSM_TOT>>>(
                phh, pWout + (size_t)li * DD*2*DH, out_br + li*DD, pxh,
                lru_ln_g + li*DD, lru_ln_b + li*DD,
                nullptr, px2h, item_len, MTOK, 128, 512);
            hmma_gemm<1><<<dim3(4, MTOK/128), 256, GSM_TOT>>>(
                px2h, pw1 + (size_t)li * DFF*DD, b1 + li*DFF, nullptr, nullptr, nullptr,
                nullptr, phfh, item_len, MTOK, 512, 128);
            hmma_gemm<2><<<dim3(1, MTOK/128), 256, GSM_TOT>>>(
                phfh, pw2 + (size_t)li * DD*DFF, b2 + li*DD, px2h,
                ffn_ln_g + li*DD, ffn_ln_b + li*DD,
                nullptr, pxh, item_len, MTOK, 128, 512);
        } else {
            gather_kernel<<<BB, 512>>>(phh, pxh, item_len, phgh, pxgh);
            hmma_gemm<2><<<dim3(1, BB/128), 256, GSM_TOT>>>(
                phgh, pWout + (size_t)li * DD*2*DH, out_br + li*DD, pxgh,
                lru_ln_g + li*DD, lru_ln_b + li*DD,
                nullptr, psm1h, nullptr, BB, 128, 512);
            hmma_gemm<1><<<dim3(4, BB/128), 256, GSM_TOT>>>(
                psm1h, pw1 + (size_t)li * DFF*DD, b1 + li*DFF, nullptr, nullptr, nullptr,
                nullptr, psm2h, nullptr, BB, 512, 128);
            hmma_gemm<2><<<dim3(1, BB/128), 256, GSM_TOT>>>(
                psm2h, pw2 + (size_t)li * DD*DFF, b2 + li*DD, psm1h,
                ffn_ln_g + li*DD, ffn_ln_b + li*DD,
                out, nullptr, nullptr, BB, 128, 512);
        }
    }
}

// round 14
// speedup vs baseline: 1.1280x; 1.0128x over previous
#include <cuda_runtime.h>
#include <cuda_bf16.h>
#include <cuda_fp16.h>
#include <math.h>
#include <stdint.h>

// Problem constants
#define BB   512
#define SS   200
#define DD   128
#define NLAY 2
#define DH   256      // complex hidden (512 reals)
#define DFF  512
#define LPAD 256
#define PAD  56
#define MTOK (BB*LPAD)

typedef __half fp16;

// single dynamic-smem symbol shared by all kernels
extern __shared__ __align__(16) char dyn_smem[];

// ---------------- scratch (device globals) ------------------------------------
__device__ fp16 g_xh [MTOK * DD];
__device__ fp16 g_x2h[MTOK * DD];
__device__ fp16 g_hh [MTOK * 2*DH];
__device__ fp16 g_hfh[MTOK * DFF];
// packed weights for BOTH layers + lambda tables [li][grp 0..7][p-1][c 0..31]
__device__ fp16 g_Win[NLAY*2*DH*DD];
__device__ float g_bin[NLAY*2*DH];
__device__ fp16 g_Wout[NLAY*DD*2*DH];
__device__ fp16 g_w1[NLAY*DFF*DD];
__device__ fp16 g_w2[NLAY*DD*DFF];
__device__ float g_lamR[NLAY*8*128*32];
__device__ float g_lamI[NLAY*8*128*32];
// layer-2 tail (gathered, M=BB)
__device__ fp16 g_xgh[BB * DD];
__device__ fp16 g_sm1h[BB*DD];
__device__ fp16 g_sm2h[BB*DFF];
__device__ fp16 g_hgh[BB*2*DH];

// ---------------- helpers -------------------------------------------------------
__device__ __forceinline__ uint32_t smem_u32(const void* p) {
    uint32_t a;
    asm("{ .reg .u64 t; cvta.to.shared.u64 t, %1; cvt.u32.u64 %0, t; }" : "=r"(a) : "l"(p));
    return a;
}
__device__ __forceinline__ void cp_async16(uint32_t s, const void* g) {
    asm volatile("cp.async.cg.shared.global [%0], [%1], 16;" :: "r"(s), "l"(g));
}
__device__ __forceinline__ void ldsm4(uint32_t (&r)[4], uint32_t addr) {
    asm volatile("ldmatrix.sync.aligned.m8n8.x4.shared.b16 {%0,%1,%2,%3}, [%4];"
                 : "=r"(r[0]), "=r"(r[1]), "=r"(r[2]), "=r"(r[3]) : "r"(addr));
}
__device__ __forceinline__ void mma16816(float* c, const uint32_t* a, uint32_t b0, uint32_t b1) {
    asm volatile("mma.sync.aligned.m16n8k16.row.col.f32.f16.f16.f32 "
                 "{%0,%1,%2,%3}, {%4,%5,%6,%7}, {%8,%9}, {%0,%1,%2,%3};"
                 : "+f"(c[0]), "+f"(c[1]), "+f"(c[2]), "+f"(c[3])
                 : "r"(a[0]), "r"(a[1]), "r"(a[2]), "r"(a[3]), "r"(b0), "r"(b1));
}
__device__ __forceinline__ void packh2(float a, float b, fp16* H, size_t idx) {
    *reinterpret_cast<__half2*>(H + idx) = __floats2half2_rn(a, b);
}

#define SM_FIX 1536
#define GP     144                // 64 fp16 = 128B + 16B pad (ldsm conflict-free)
#define GTILE  (128*GP)           // 18432
#define GSTAGE (2*GTILE)          // 36864 (A + B)
#define NSTAGE 3
#define GSM_TOT (SM_FIX + NSTAGE*GSTAGE)   // 112128 -> 2 CTAs/SM

// low-register BN=64 variant (K=128 GEMMs only)
#define G2A     (128*GP)          // 18432
#define G2B     (64*GP)           // 9216
#define G2STAGE (G2A + G2B)       // 27648
#define G2SM    (SM_FIX + 2*G2STAGE)  // 56832 -> 3 CTAs/SM (reg-capped)

// ---------------- embedding gather + LN + front-pad (warp per token) ------------
__global__ void embed_kernel(const float* __restrict__ emb,
                             const float* __restrict__ g,
                             const float* __restrict__ bta,
                             const int*   __restrict__ seq,
                             fp16* __restrict__ xh) {
    int gidx = blockIdx.x * 8 + (threadIdx.x >> 5);
    int lane = threadIdx.x & 31;
    int b = gidx >> 8, t = gidx & 255;
    size_t o = (size_t)gidx * DD + lane * 4;
    if (t < PAD) {
        *reinterpret_cast<uint2*>(&xh[o]) = make_uint2(0u, 0u);
        return;
    }
    int item = seq[b * SS + (t - PAD)];
    float4 v = *reinterpret_cast<const float4*>(emb + (size_t)item * DD + lane * 4);
    float s = v.x + v.y + v.z + v.w;
    #pragma unroll
    for (int off = 16; off > 0; off >>= 1) s += __shfl_xor_sync(0xffffffffu, s, off);
    float mu = s * (1.f / DD);
    float dx = v.x - mu, dy = v.y - mu, dz = v.z - mu, dw = v.w - mu;
    float qq = dx*dx + dy*dy + dz*dz + dw*dw;
    #pragma unroll
    for (int off = 16; off > 0; off >>= 1) qq += __shfl_xor_sync(0xffffffffu, qq, off);
    float rs = rsqrtf(qq * (1.f / DD) + 1e-5f);
    float4 gg = *reinterpret_cast<const float4*>(g + lane * 4);
    float4 bb = *reinterpret_cast<const float4*>(bta + lane * 4);
    __half2 h01 = __floats2half2_rn(dx * rs * gg.x + bb.x, dy * rs * gg.y + bb.y);
    __half2 h23 = __floats2half2_rn(dz * rs * gg.z + bb.z, dw * rs * gg.w + bb.w);
    uint2 pk;
    pk.x = *reinterpret_cast<uint32_t*>(&h01);
    pk.y = *reinterpret_cast<uint32_t*>(&h23);
    *reinterpret_cast<uint2*>(&xh[o]) = pk;
}

// ---------------- lambda-power table (one layer per launch) ---------------------
__global__ void lam_kernel(const float* __restrict__ params_log, int li) {
    int idx = blockIdx.x * 256 + threadIdx.x;
    int cg = idx >> 12, rem = idx & 4095;
    int p = (rem >> 5) + 1, c = rem & 31;
    int d = cg * 32 + c;
    float nu = expf(params_log[(li * 3 + 0) * DH + d]);
    float th = expf(params_log[(li * 3 + 1) * DH + d]);
    float mag = expf(-nu * (float)p);
    float sv, cv;
    sincosf(th * (float)p, &sv, &cv);
    g_lamR[li * 32768 + idx] = mag * cv;
    g_lamI[li * 32768 + idx] = mag * sv;
}

// ---------------- weight packing (one layer per launch, to fp16) ----------------
__global__ void pack_kernel(const float* __restrict__ in_wr, const float* __restrict__ in_wi,
                            const float* __restrict__ in_br, const float* __restrict__ in_bi,
                            const float* __restrict__ out_wr, const float* __restrict__ out_wi,
                            const float* __restrict__ w1, const float* __restrict__ w2,
                            const float* __restrict__ params_log, int li) {
    int idx = blockIdx.x * 256 + threadIdx.x;
    int mat = idx >> 16, r = idx & 65535;
    float w;
    fp16* Dst;
    if (mat == 0) {
        int n = r >> 7, k = r & 127;
        int d = n >> 1, s = n & 1;
        float gamma = expf(params_log[(li * 3 + 2) * DH + d]);
        w = (s ? in_wi[(size_t)li * DH * DD + d * DD + k]
               : in_wr[(size_t)li * DH * DD + d * DD + k]) * gamma;
        if (k == 0) {
            float bv = s ? in_bi[li * DH + d] : in_br[li * DH + d];
            g_bin[li * 2*DH + n] = bv * gamma;
        }
        Dst = g_Win + (size_t)li * 2*DH*DD;
    } else if (mat == 1) {
        int n = r >> 9, k = r & 511;
        int d = k >> 1, s = k & 1;
        w = s ? -out_wi[(size_t)li * DD * DH + n * DH + d]
              :  out_wr[(size_t)li * DD * DH + n * DH + d];
        Dst = g_Wout + (size_t)li * DD*2*DH;
    } else if (mat == 2) {
        w = w1[(size_t)li * DFF * DD + r];
        Dst = g_w1 + (size_t)li * DFF*DD;
    } else {
        w = w2[(size_t)li * DD * DFF + r];
        Dst = g_w2 + (size_t)li * DD*DFF;
    }
    Dst[r] = __float2half_rn(w);
}

// ---------------- gather last valid token --------------------------------------
__global__ void gather_kernel(const fp16* __restrict__ hh,
                              const fp16* __restrict__ xh, const int* __restrict__ slen,
                              fp16* __restrict__ hgh, fp16* __restrict__ xgh) {
    int b = blockIdx.x, tid = threadIdx.x;
    int t = PAD + slen[b] - 1;
    hgh[(size_t)b * 512 + tid] = hh[((size_t)b * LPAD + t) * 512 + tid];
    if (tid < DD) xgh[(size_t)b * DD + tid] = xh[((size_t)b * LPAD + t) * DD + tid];
}

// ================= register-resident masked LRU tree scan =======================
__global__ void __launch_bounds__(256) scan_kernel(fp16* __restrict__ hh,
                                                   const int* __restrict__ seq,
                                                   const int* __restrict__ slen, int li) {
    __shared__ float ms[LPAD];
    __shared__ float2 bnd[8][32];
    int b = blockIdx.y, cg = blockIdx.x;
    int tid = threadIdx.x;
    int c = tid & 31, tc = tid >> 5;
    const float* lamR = g_lamR + ((size_t)li * 8 + cg) * 4096;
    const float* lamI = g_lamI + ((size_t)li * 8 + cg) * 4096;

    ms[tid] = (tid >= PAD && seq[b * SS + tid - PAD] > 0) ? 1.f : 0.f;
    int tb = PAD + slen[b] - 1;

    int t0 = tc * 32;
    bool live = (t0 <= tb);
    size_t base = ((size_t)b * LPAD + t0) * 512 + cg * 64 + 2 * c;
    float2 h[32];
    if (live) {
        #pragma unroll
        for (int j = 0; j < 32; j++)
            h[j] = __half22float2(*reinterpret_cast<const __half2*>(hh + base + (size_t)j * 512));
    } else {
        #pragma unroll
        for (int j = 0; j < 32; j++) h[j] = make_float2(0.f, 0.f);
    }
    __syncthreads();

    #pragma unroll
    for (int lev = 1; lev <= 5; lev++) {
        int half = 1 << (lev - 1);
        #pragma unroll
        for (int s = 0; s < 32; s += (1 << lev)) {
            int cpos = t0 + s + half - 1;
            if (ms[cpos] != 0.f) {
                float2 src = h[s + half - 1];
                #pragma unroll
                for (int p = 1; p <= (1 << (lev - 1)); p++) {
                    int j = s + half - 1 + p;
                    float lr = lamR[(p - 1) * 32 + c], liw = lamI[(p - 1) * 32 + c];
                    h[j].x += lr * src.x - liw * src.y;
                    h[j].y += lr * src.y + liw * src.x;
                }
            }
        }
    }

    bnd[tc][c] = h[31];
    __syncthreads();
    #pragma unroll
    for (int lev = 6; lev <= 8; lev++) {
        int l = 1 << lev, half = l >> 1;
        int blk = t0 >> lev;
        int cpos = blk * l + half - 1;
        if (live && t0 > cpos && ms[cpos] != 0.f) {
            float2 src = bnd[cpos >> 5][c];
            int p0 = t0 - cpos;
            #pragma unroll
            for (int j = 0; j < 32; j++) {
                int p = p0 + j;
                float lr = lamR[(p - 1) * 32 + c], liw = lamI[(p - 1) * 32 + c];
                h[j].x += lr * src.x - liw * src.y;
                h[j].y += lr * src.y + liw * src.x;
            }
            bnd[tc][c] = h[31];
        }
        __syncthreads();
    }

    if (live) {
        #pragma unroll
        for (int j = 0; j < 32; j++)
            *reinterpret_cast<__half2*>(hh + base + (size_t)j * 512) =
                __floats2half2_rn(h[j].x, h[j].y);
    }
}

// ============ low-register BN=64 fp16 GEMM, K=128 fixed, 3 CTAs/SM ==============
// Block 128x64, 8 warps, warp tile 32x32 (4m x 2n), acc = 32 regs.
// Both K-chunks prefetched upfront; no mid-loop loads.
// EPI 0: bias. EPI 1: bias + gelu. Output fp16.
template<int EPI>
__global__ void __launch_bounds__(256, 3) hmma_gemm64(
        const fp16* __restrict__ A, const fp16* __restrict__ B,
        const float* __restrict__ bias, fp16* __restrict__ Ch,
        const int* __restrict__ lenp, int M, int N) {
    if (lenp && (blockIdx.y & 1) && lenp[blockIdx.y >> 1] < 73) return;

    char* sm = dyn_smem;
    float* sBias = (float*)sm;
    uint32_t sb = smem_u32(sm);
    int tid = threadIdx.x, lane = tid & 31, wid = tid >> 5;
    int q = lane & 3, hrow = lane >> 2;
    int wm = wid & 3, wn = wid >> 2;
    int m0 = blockIdx.y * 128, n0 = blockIdx.x * 64;

    #pragma unroll
    for (int c = 0; c < 2; c++) {
        uint32_t st = sb + SM_FIX + c * G2STAGE;
        int kc = c * 64;
        #pragma unroll
        for (int t = 0; t < 6; t++) {
            int idx = tid + t * 256;        // 0..1535
            if (idx < 1024) {
                int row = idx >> 3, seg = idx & 7;
                cp_async16(st + row * GP + seg * 16,
                           A + (size_t)(m0 + row) * 128 + kc + seg * 8);
            } else {
                int r = idx - 1024;
                int row = r >> 3, seg = r & 7;
                cp_async16(st + G2A + row * GP + seg * 16,
                           B + (size_t)(n0 + row) * 128 + kc + seg * 8);
            }
        }
        asm volatile("cp.async.commit_group;");
    }
    if (tid < 64) sBias[tid] = bias[n0 + tid];

    float acc[2][4][4];
    #pragma unroll
    for (int a1 = 0; a1 < 2; a1++)
        #pragma unroll
        for (int a2 = 0; a2 < 4; a2++)
            #pragma unroll
            for (int a3 = 0; a3 < 4; a3++) acc[a1][a2][a3] = 0.f;

    #pragma unroll
    for (int ch = 0; ch < 2; ch++) {
        if (ch == 0) asm volatile("cp.async.wait_group 1;");
        else         asm volatile("cp.async.wait_group 0;");
        __syncthreads();
        uint32_t st = sb + SM_FIX + ch * G2STAGE;
        #pragma unroll
        for (int ks = 0; ks < 4; ks++) {
            uint32_t ah[2][4];
            #pragma unroll
            for (int mt = 0; mt < 2; mt++) {
                uint32_t aoff = (uint32_t)((wm*32 + mt*16 + (lane & 15)) * GP + ks*32 + (lane >> 4) * 16);
                ldsm4(ah[mt], st + aoff);
            }
            #pragma unroll
            for (int nb = 0; nb < 2; nb++) {
                uint32_t boff = (uint32_t)((wn*32 + nb*16 + (lane & 15)) * GP + ks*32 + (lane >> 4) * 16);
                uint32_t bh[4];
                ldsm4(bh, st + G2A + boff);
                #pragma unroll
                for (int mt = 0; mt < 2; mt++) {
                    mma16816(acc[mt][2*nb],   ah[mt], bh[0], bh[2]);
                    mma16816(acc[mt][2*nb+1], ah[mt], bh[1], bh[3]);
                }
            }
        }
    }

    // epilogue
    #pragma unroll
    for (int mt = 0; mt < 2; mt++) {
        int r0 = m0 + wm*32 + mt*16 + hrow;
        #pragma unroll
        for (int j = 0; j < 4; j++) {
            int col = wn*32 + j*8 + q*2;
            float b0 = sBias[col], b1 = sBias[col+1];
            float v0 = acc[mt][j][0] + b0, v1 = acc[mt][j][1] + b1;
            float v2 = acc[mt][j][2] + b0, v3 = acc[mt][j][3] + b1;
            if (EPI == 1) {
                v0 = 0.5f * v0 * (1.f + erff(v0 * 0.70710678118654752f));
                v1 = 0.5f * v1 * (1.f + erff(v1 * 0.70710678118654752f));
                v2 = 0.5f * v2 * (1.f + erff(v2 * 0.70710678118654752f));
                v3 = 0.5f * v3 * (1.f + erff(v3 * 0.70710678118654752f));
            }
            packh2(v0, v1, Ch, (size_t)r0 * N + n0 + col);
            packh2(v2, v3, Ch, (size_t)(r0+8) * N + n0 + col);
        }
    }
}

// ================= pipelined fp16 GEMM BN=128 (K=512 GEMMs) =====================
// EPI 1: bias+gelu. EPI 2: bias+residual(fp16)+LayerNorm (N==128).
__device__ __forceinline__ void gemm_load_chunk(
        uint32_t st, const fp16* A, const fp16* B,
        int m0, int n0, int kc, int K, int tid) {
    #pragma unroll
    for (int t = 0; t < 4; t++) {
        int idx = tid + t * 256;
        int row = idx >> 3, seg = idx & 7;
        uint32_t so = row * GP + seg * 16;
        cp_async16(st + so,         A + (size_t)(m0 + row) * K + kc + seg * 8);
        cp_async16(st + GTILE + so, B + (size_t)(n0 + row) * K + kc + seg * 8);
    }
}

template<int EPI>
__global__ void __launch_bounds__(256, 2) hmma_gemm(
        const fp16* __restrict__ A, const fp16* __restrict__ B,
        const float* __restrict__ bias, const fp16* __restrict__ Res,
        const float* __restrict__ lng, const float* __restrict__ lnb,
        float* __restrict__ Cf, fp16* __restrict__ Ch,
        const int* __restrict__ lenp,
        int M, int N, int K) {
    if (lenp && (blockIdx.y & 1) && lenp[blockIdx.y >> 1] < 73) return;

    char* sm = dyn_smem;
    float* sBias = (float*)sm;
    float* sG    = sBias + 128;
    float* sB    = sG + 128;
    float* sred  = (float*)(sm + SM_FIX);
    uint32_t sb = smem_u32(sm);

    int tid = threadIdx.x, lane = tid & 31, wid = tid >> 5;
    int q = lane & 3, hrow = lane >> 2;
    int wm = wid & 3, wn = wid >> 2;
    int m0 = blockIdx.y * 128, n0 = blockIdx.x * 128;

    if (tid < 128) {
        sBias[tid] = bias[n0 + tid];
        if (EPI == 2) { sG[tid] = lng[n0 + tid]; sB[tid] = lnb[n0 + tid]; }
    }

    float acc[2][8][4];
    #pragma unroll
    for (int a1 = 0; a1 < 2; a1++)
        #pragma unroll
        for (int a2 = 0; a2 < 8; a2++)
            #pragma unroll
            for (int a3 = 0; a3 < 4; a3++) acc[a1][a2][a3] = 0.f;

    int nc = K >> 6;
    gemm_load_chunk(sb + SM_FIX, A, B, m0, n0, 0, K, tid);
    asm volatile("cp.async.commit_group;");
    if (nc > 1) gemm_load_chunk(sb + SM_FIX + GSTAGE, A, B, m0, n0, 64, K, tid);
    asm volatile("cp.async.commit_group;");

    for (int ch = 0; ch < nc; ch++) {
        asm volatile("cp.async.wait_group 1;");
        __syncthreads();
        uint32_t st = sb + SM_FIX + (ch % NSTAGE) * GSTAGE;
        uint32_t aA = st, aB = st + GTILE;
        #pragma unroll
        for (int ks = 0; ks < 4; ks++) {
            uint32_t ah[2][4];
            #pragma unroll
            for (int mt = 0; mt < 2; mt++) {
                uint32_t aoff = (uint32_t)((wm*32 + mt*16 + (lane & 15)) * GP + ks*32 + (lane >> 4) * 16);
                ldsm4(ah[mt], aA + aoff);
            }
            #pragma unroll
            for (int nb = 0; nb < 4; nb++) {
                uint32_t boff = (uint32_t)((wn*64 + nb*16 + (lane & 15)) * GP + ks*32 + (lane >> 4) * 16);
                uint32_t bh[4];
                ldsm4(bh, aB + boff);
                #pragma unroll
                for (int mt = 0; mt < 2; mt++) {
                    mma16816(acc[mt][2*nb],   ah[mt], bh[0], bh[2]);
                    mma16816(acc[mt][2*nb+1], ah[mt], bh[1], bh[3]);
                }
            }
        }
        if (ch + 2 < nc)
            gemm_load_chunk(sb + SM_FIX + ((ch + 2) % NSTAGE) * GSTAGE,
                            A, B, m0, n0, (ch + 2) << 6, K, tid);
        asm volatile("cp.async.commit_group;");
    }
    __syncthreads();

    // ---------------- epilogue ----------------
    #pragma unroll
    for (int mt = 0; mt < 2; mt++)
        #pragma unroll
        for (int j = 0; j < 8; j++) {
            int col = wn*64 + j*8 + q*2;
            float b0 = sBias[col], b1 = sBias[col+1];
            acc[mt][j][0] += b0; acc[mt][j][1] += b1;
            acc[mt][j][2] += b0; acc[mt][j][3] += b1;
        }
    if (EPI == 1) {
        #pragma unroll
        for (int mt = 0; mt < 2; mt++)
            #pragma unroll
            for (int j = 0; j < 8; j++)
                #pragma unroll
                for (int v = 0; v < 4; v++)
                    acc[mt][j][v] = 0.5f * acc[mt][j][v] *
                                    (1.f + erff(acc[mt][j][v] * 0.70710678118654752f));
    }
    if (EPI == 2) {
        float mu[2][2], rs[2][2];
        #pragma unroll
        for (int mt = 0; mt < 2; mt++) {
            int r0 = m0 + wm*32 + mt*16 + hrow;
            #pragma unroll
            for (int j = 0; j < 8; j++) {
                int col = wn*64 + j*8 + q*2;
                float2 ra = __half22float2(*(const __half2*)(Res + (size_t)r0 * 128 + col));
                float2 rb = __half22float2(*(const __half2*)(Res + (size_t)(r0+8) * 128 + col));
                acc[mt][j][0] += ra.x; acc[mt][j][1] += ra.y;
                acc[mt][j][2] += rb.x; acc[mt][j][3] += rb.y;
            }
        }
        float ssum[2][2] = {{0,0},{0,0}}, ssq[2][2] = {{0,0},{0,0}};
        #pragma unroll
        for (int mt = 0; mt < 2; mt++)
            #pragma unroll
            for (int j = 0; j < 8; j++)
                #pragma unroll
                for (int hh = 0; hh < 2; hh++) {
                    float v0 = acc[mt][j][2*hh], v1 = acc[mt][j][2*hh+1];
                    ssum[mt][hh] += v0 + v1;
                    ssq[mt][hh]  += v0*v0 + v1*v1;
                }
        #pragma unroll
        for (int mt = 0; mt < 2; mt++)
            #pragma unroll
            for (int hh = 0; hh < 2; hh++) {
                ssum[mt][hh] += __shfl_xor_sync(0xffffffffu, ssum[mt][hh], 1);
                ssum[mt][hh] += __shfl_xor_sync(0xffffffffu, ssum[mt][hh], 2);
                ssq[mt][hh]  += __shfl_xor_sync(0xffffffffu, ssq[mt][hh], 1);
                ssq[mt][hh]  += __shfl_xor_sync(0xffffffffu, ssq[mt][hh], 2);
            }
        if (q == 0) {
            #pragma unroll
            for (int mt = 0; mt < 2; mt++)
                #pragma unroll
                for (int hh = 0; hh < 2; hh++) {
                    int lr = wm*32 + mt*16 + hrow + hh*8;
                    sred[lr*2 + wn]       = ssum[mt][hh];
                    sred[256 + lr*2 + wn] = ssq[mt][hh];
                }
        }
        __syncthreads();
        #pragma unroll
        for (int mt = 0; mt < 2; mt++)
            #pragma unroll
            for (int hh = 0; hh < 2; hh++) {
                int lr = wm*32 + mt*16 + hrow + hh*8;
                float S  = sred[lr*2] + sred[lr*2 + 1];
                float S2 = sred[256 + lr*2] + sred[256 + lr*2 + 1];
                float m  = S * (1.f/128.f);
                float var = S2 * (1.f/128.f) - m * m;
                mu[mt][hh] = m;
                rs[mt][hh] = rsqrtf(var + 1e-5f);
            }
        #pragma unroll
        for (int mt = 0; mt < 2; mt++)
            #pragma unroll
            for (int j = 0; j < 8; j++) {
                int col = wn*64 + j*8 + q*2;
                float g0 = sG[col], g1 = sG[col+1], bb0 = sB[col], bb1 = sB[col+1];
                acc[mt][j][0] = (acc[mt][j][0] - mu[mt][0]) * rs[mt][0] * g0 + bb0;
                acc[mt][j][1] = (acc[mt][j][1] - mu[mt][0]) * rs[mt][0] * g1 + bb1;
                acc[mt][j][2] = (acc[mt][j][2] - mu[mt][1]) * rs[mt][1] * g0 + bb0;
                acc[mt][j][3] = (acc[mt][j][3] - mu[mt][1]) * rs[mt][1] * g1 + bb1;
            }
    }
    #pragma unroll
    for (int mt = 0; mt < 2; mt++) {
        int r0 = m0 + wm*32 + mt*16 + hrow;
        #pragma unroll
        for (int j = 0; j < 8; j++) {
            int col = n0 + wn*64 + j*8 + q*2;
            if (Cf) {
                *(float2*)(Cf + (size_t)r0 * N + col)     = make_float2(acc[mt][j][0], acc[mt][j][1]);
                *(float2*)(Cf + (size_t)(r0+8) * N + col) = make_float2(acc[mt][j][2], acc[mt][j][3]);
            }
            if (Ch) {
                packh2(acc[mt][j][0], acc[mt][j][1], Ch, (size_t)r0 * N + col);
                packh2(acc[mt][j][2], acc[mt][j][3], Ch, (size_t)(r0+8) * N + col);
            }
        }
    }
}

// ---------------- host driver ---------------------------------------------------
extern "C" void kernel_launch(void* const* d_in, const int* in_sizes, int n_in,
                              void* d_out, int out_size) {
    const float* token_emb  = (const float*)d_in[0];
    const float* emb_ln_g   = (const float*)d_in[1];
    const float* emb_ln_b   = (const float*)d_in[2];
    const float* params_log = (const float*)d_in[3];
    const float* in_wr      = (const float*)d_in[4];
    const float* in_wi      = (const float*)d_in[5];
    const float* in_br      = (const float*)d_in[6];
    const float* in_bi      = (const float*)d_in[7];
    const float* out_wr     = (const float*)d_in[8];
    const float* out_wi     = (const float*)d_in[9];
    const float* out_br     = (const float*)d_in[10];
    const float* lru_ln_g   = (const float*)d_in[12];
    const float* lru_ln_b   = (const float*)d_in[13];
    const float* w1         = (const float*)d_in[14];
    const float* b1         = (const float*)d_in[15];
    const float* w2         = (const float*)d_in[16];
    const float* b2         = (const float*)d_in[17];
    const float* ffn_ln_g   = (const float*)d_in[18];
    const float* ffn_ln_b   = (const float*)d_in[19];
    const int*   item_seq   = (const int*)d_in[20];
    const int*   item_len   = (const int*)d_in[21];
    float* out = (float*)d_out;

    float *pbin;
    fp16 *pxh, *px2h, *phh, *phfh, *pWin, *pWout, *pw1, *pw2;
    fp16 *psm1h, *psm2h, *phgh, *pxgh;
    cudaGetSymbolAddress((void**)&pxh,   g_xh);
    cudaGetSymbolAddress((void**)&px2h,  g_x2h);
    cudaGetSymbolAddress((void**)&phh,   g_hh);
    cudaGetSymbolAddress((void**)&phfh,  g_hfh);
    cudaGetSymbolAddress((void**)&pWin,  g_Win);
    cudaGetSymbolAddress((void**)&pbin,  g_bin);
    cudaGetSymbolAddress((void**)&pWout, g_Wout);
    cudaGetSymbolAddress((void**)&pw1,   g_w1);
    cudaGetSymbolAddress((void**)&pw2,   g_w2);
    cudaGetSymbolAddress((void**)&pxgh,  g_xgh);
    cudaGetSymbolAddress((void**)&psm1h, g_sm1h);
    cudaGetSymbolAddress((void**)&psm2h, g_sm2h);
    cudaGetSymbolAddress((void**)&phgh,  g_hgh);

    cudaFuncSetAttribute(hmma_gemm<1>, cudaFuncAttributeMaxDynamicSharedMemorySize, GSM_TOT);
    cudaFuncSetAttribute(hmma_gemm<2>, cudaFuncAttributeMaxDynamicSharedMemorySize, GSM_TOT);
    cudaFuncSetAttribute(hmma_gemm64<0>, cudaFuncAttributeMaxDynamicSharedMemorySize, G2SM);
    cudaFuncSetAttribute(hmma_gemm64<1>, cudaFuncAttributeMaxDynamicSharedMemorySize, G2SM);

    // pack weights + lambda tables for both layers up front
    for (int li = 0; li < NLAY; li++) {
        pack_kernel<<<1024, 256>>>(in_wr, in_wi, in_br, in_bi, out_wr, out_wi,
                                   w1, w2, params_log, li);
        lam_kernel<<<128, 256>>>(params_log, li);
    }
    embed_kernel<<<MTOK/8, 256>>>(token_emb, emb_ln_g, emb_ln_b, item_seq, pxh);

    for (int li = 0; li < NLAY; li++) {
        // in-projection (bias folded, fp16 out, interleaved complex columns)
        hmma_gemm64<0><<<dim3(8, MTOK/128), 256, G2SM>>>(
            pxh, pWin + (size_t)li * 2*DH*DD, pbin + li * 2*DH,
            phh, item_len, MTOK, 512);
        // masked LRU tree scan, register-resident, in place
        scan_kernel<<<dim3(8, BB), 256>>>(phh, item_seq, item_len, li);

        if (li == 0) {
            hmma_gemm<2><<<dim3(1, MTOK/128), 256, GSM_TOT>>>(
                phh, pWout + (size_t)li * DD*2*DH, out_br + li*DD, pxh,
                lru_ln_g + li*DD, lru_ln_b + li*DD,
                nullptr, px2h, item_len, MTOK, 128, 512);
            hmma_gemm64<1><<<dim3(8, MTOK/128), 256, G2SM>>>(
                px2h, pw1 + (size_t)li * DFF*DD, b1 + li*DFF,
                phfh, item_len, MTOK, 512);
            hmma_gemm<2><<<dim3(1, MTOK/128), 256, GSM_TOT>>>(
                phfh, pw2 + (size_t)li * DD*DFF, b2 + li*DD, px2h,
                ffn_ln_g + li*DD, ffn_ln_b + li*DD,
                nullptr, pxh, item_len, MTOK, 128, 512);
        } else {
            gather_kernel<<<BB, 512>>>(phh, pxh, item_len, phgh, pxgh);
            hmma_gemm<2><<<dim3(1, BB/128), 256, GSM_TOT>>>(
                phgh, pWout + (size_t)li * DD*2*DH, out_br + li*DD, pxgh,
                lru_ln_g + li*DD, lru_ln_b + li*DD,
                nullptr, psm1h, nullptr, BB, 128, 512);
            hmma_gemm64<1><<<dim3(8, BB/128), 256, G2SM>>>(
                psm1h, pw1 + (size_t)li * DFF*DD, b1 + li*DFF,
                psm2h, nullptr, BB, 512);
            hmma_gemm<2><<<dim3(1, BB/128), 256, GSM_TOT>>>(
                psm2h, pw2 + (size_t)li * DD*DFF, b2 + li*DD, psm1h,
                ffn_ln_g + li*DD, ffn_ln_b + li*DD,
                out, nullptr, nullptr, BB, 128, 512);
        }
    }
}

// round 15
// speedup vs baseline: 1.1323x; 1.0037x over previous
#include <cuda_runtime.h>
#include <cuda_bf16.h>
#include <cuda_fp16.h>
#include <math.h>
#include <stdint.h>

// Problem constants
#define BB   512
#define SS   200
#define DD   128
#define NLAY 2
#define DH   256      // complex hidden (512 reals)
#define DFF  512
#define LPAD 256
#define PAD  56
#define MTOK (BB*LPAD)

typedef __half fp16;

// single dynamic-smem symbol shared by all kernels
extern __shared__ __align__(16) char dyn_smem[];

// ---------------- scratch (device globals) ------------------------------------
__device__ fp16 g_xh [MTOK * DD];
__device__ fp16 g_x2h[MTOK * DD];
__device__ fp16 g_hh [MTOK * 2*DH];
// packed weights for BOTH layers + lambda tables [li][grp 0..7][p-1][c 0..31]
__device__ fp16 g_Win[NLAY*2*DH*DD];
__device__ float g_bin[NLAY*2*DH];
__device__ fp16 g_Wout[NLAY*DD*2*DH];
__device__ fp16 g_w1[NLAY*DFF*DD];
__device__ fp16 g_w2[NLAY*DD*DFF];
__device__ float g_lamR[NLAY*8*128*32];
__device__ float g_lamI[NLAY*8*128*32];
// layer-2 tail (gathered, M=BB)
__device__ fp16 g_xgh[BB * DD];
__device__ fp16 g_sm1h[BB*DD];
__device__ fp16 g_hgh[BB*2*DH];

// ---------------- helpers -------------------------------------------------------
__device__ __forceinline__ uint32_t smem_u32(const void* p) {
    uint32_t a;
    asm("{ .reg .u64 t; cvta.to.shared.u64 t, %1; cvt.u32.u64 %0, t; }" : "=r"(a) : "l"(p));
    return a;
}
__device__ __forceinline__ void cp_async16(uint32_t s, const void* g) {
    asm volatile("cp.async.cg.shared.global [%0], [%1], 16;" :: "r"(s), "l"(g));
}
__device__ __forceinline__ void ldsm4(uint32_t (&r)[4], uint32_t addr) {
    asm volatile("ldmatrix.sync.aligned.m8n8.x4.shared.b16 {%0,%1,%2,%3}, [%4];"
                 : "=r"(r[0]), "=r"(r[1]), "=r"(r[2]), "=r"(r[3]) : "r"(addr));
}
__device__ __forceinline__ void mma16816(float* c, const uint32_t* a, uint32_t b0, uint32_t b1) {
    asm volatile("mma.sync.aligned.m16n8k16.row.col.f32.f16.f16.f32 "
                 "{%0,%1,%2,%3}, {%4,%5,%6,%7}, {%8,%9}, {%0,%1,%2,%3};"
                 : "+f"(c[0]), "+f"(c[1]), "+f"(c[2]), "+f"(c[3])
                 : "r"(a[0]), "r"(a[1]), "r"(a[2]), "r"(a[3]), "r"(b0), "r"(b1));
}
__device__ __forceinline__ void packh2(float a, float b, fp16* H, size_t idx) {
    *reinterpret_cast<__half2*>(H + idx) = __floats2half2_rn(a, b);
}

#define SM_FIX 1536
#define GP     144                // 64 fp16 = 128B + 16B pad (ldsm conflict-free)
#define GTILE  (128*GP)           // 18432
#define GSTAGE (2*GTILE)          // 36864 (A + B)
#define NSTAGE 3
#define GSM_TOT (SM_FIX + NSTAGE*GSTAGE)   // 112128 -> 2 CTAs/SM

// low-register BN=64 variant (K=128 GEMMs)
#define G2A     (128*GP)
#define G2B     (64*GP)
#define G2STAGE (G2A + G2B)
#define G2SM    (SM_FIX + 2*G2STAGE)  // 56832 -> 3 CTAs/SM (reg-capped)

// fused FFN
#define F2_FIX 3584
#define F2_X   F2_FIX                  // 2 x 18432
#define F2_W1  (F2_FIX + 36864)        // 2 x 9216
#define F2_HF  (F2_W1 + 18432)         // 18432
#define F2_W2  (F2_HF + 18432)         // 18432
#define F2_SM  (F2_W2 + 18432)         // 95744 -> 2 CTAs/SM

// ---------------- embedding gather + LN + front-pad (warp per token) ------------
__global__ void embed_kernel(const float* __restrict__ emb,
                             const float* __restrict__ g,
                             const float* __restrict__ bta,
                             const int*   __restrict__ seq,
                             fp16* __restrict__ xh) {
    int gidx = blockIdx.x * 8 + (threadIdx.x >> 5);
    int lane = threadIdx.x & 31;
    int b = gidx >> 8, t = gidx & 255;
    size_t o = (size_t)gidx * DD + lane * 4;
    if (t < PAD) {
        *reinterpret_cast<uint2*>(&xh[o]) = make_uint2(0u, 0u);
        return;
    }
    int item = seq[b * SS + (t - PAD)];
    float4 v = *reinterpret_cast<const float4*>(emb + (size_t)item * DD + lane * 4);
    float s = v.x + v.y + v.z + v.w;
    #pragma unroll
    for (int off = 16; off > 0; off >>= 1) s += __shfl_xor_sync(0xffffffffu, s, off);
    float mu = s * (1.f / DD);
    float dx = v.x - mu, dy = v.y - mu, dz = v.z - mu, dw = v.w - mu;
    float qq = dx*dx + dy*dy + dz*dz + dw*dw;
    #pragma unroll
    for (int off = 16; off > 0; off >>= 1) qq += __shfl_xor_sync(0xffffffffu, qq, off);
    float rs = rsqrtf(qq * (1.f / DD) + 1e-5f);
    float4 gg = *reinterpret_cast<const float4*>(g + lane * 4);
    float4 bb = *reinterpret_cast<const float4*>(bta + lane * 4);
    __half2 h01 = __floats2half2_rn(dx * rs * gg.x + bb.x, dy * rs * gg.y + bb.y);
    __half2 h23 = __floats2half2_rn(dz * rs * gg.z + bb.z, dw * rs * gg.w + bb.w);
    uint2 pk;
    pk.x = *reinterpret_cast<uint32_t*>(&h01);
    pk.y = *reinterpret_cast<uint32_t*>(&h23);
    *reinterpret_cast<uint2*>(&xh[o]) = pk;
}

// ---------------- lambda-power table (one layer per launch) ---------------------
__global__ void lam_kernel(const float* __restrict__ params_log, int li) {
    int idx = blockIdx.x * 256 + threadIdx.x;
    int cg = idx >> 12, rem = idx & 4095;
    int p = (rem >> 5) + 1, c = rem & 31;
    int d = cg * 32 + c;
    float nu = expf(params_log[(li * 3 + 0) * DH + d]);
    float th = expf(params_log[(li * 3 + 1) * DH + d]);
    float mag = expf(-nu * (float)p);
    float sv, cv;
    sincosf(th * (float)p, &sv, &cv);
    g_lamR[li * 32768 + idx] = mag * cv;
    g_lamI[li * 32768 + idx] = mag * sv;
}

// ---------------- weight packing (one layer per launch, to fp16) ----------------
__global__ void pack_kernel(const float* __restrict__ in_wr, const float* __restrict__ in_wi,
                            const float* __restrict__ in_br, const float* __restrict__ in_bi,
                            const float* __restrict__ out_wr, const float* __restrict__ out_wi,
                            const float* __restrict__ w1, const float* __restrict__ w2,
                            const float* __restrict__ params_log, int li) {
    int idx = blockIdx.x * 256 + threadIdx.x;
    int mat = idx >> 16, r = idx & 65535;
    float w;
    fp16* Dst;
    if (mat == 0) {
        int n = r >> 7, k = r & 127;
        int d = n >> 1, s = n & 1;
        float gamma = expf(params_log[(li * 3 + 2) * DH + d]);
        w = (s ? in_wi[(size_t)li * DH * DD + d * DD + k]
               : in_wr[(size_t)li * DH * DD + d * DD + k]) * gamma;
        if (k == 0) {
            float bv = s ? in_bi[li * DH + d] : in_br[li * DH + d];
            g_bin[li * 2*DH + n] = bv * gamma;
        }
        Dst = g_Win + (size_t)li * 2*DH*DD;
    } else if (mat == 1) {
        int n = r >> 9, k = r & 511;
        int d = k >> 1, s = k & 1;
        w = s ? -out_wi[(size_t)li * DD * DH + n * DH + d]
              :  out_wr[(size_t)li * DD * DH + n * DH + d];
        Dst = g_Wout + (size_t)li * DD*2*DH;
    } else if (mat == 2) {
        w = w1[(size_t)li * DFF * DD + r];
        Dst = g_w1 + (size_t)li * DFF*DD;
    } else {
        w = w2[(size_t)li * DD * DFF + r];
        Dst = g_w2 + (size_t)li * DD*DFF;
    }
    Dst[r] = __float2half_rn(w);
}

// ---------------- gather last valid token --------------------------------------
__global__ void gather_kernel(const fp16* __restrict__ hh,
                              const fp16* __restrict__ xh, const int* __restrict__ slen,
                              fp16* __restrict__ hgh, fp16* __restrict__ xgh) {
    int b = blockIdx.x, tid = threadIdx.x;
    int t = PAD + slen[b] - 1;
    hgh[(size_t)b * 512 + tid] = hh[((size_t)b * LPAD + t) * 512 + tid];
    if (tid < DD) xgh[(size_t)b * DD + tid] = xh[((size_t)b * LPAD + t) * DD + tid];
}

// ================= register-resident masked LRU tree scan =======================
__global__ void __launch_bounds__(256) scan_kernel(fp16* __restrict__ hh,
                                                   const int* __restrict__ seq,
                                                   const int* __restrict__ slen, int li) {
    __shared__ float ms[LPAD];
    __shared__ float2 bnd[8][32];
    int b = blockIdx.y, cg = blockIdx.x;
    int tid = threadIdx.x;
    int c = tid & 31, tc = tid >> 5;
    const float* lamR = g_lamR + ((size_t)li * 8 + cg) * 4096;
    const float* lamI = g_lamI + ((size_t)li * 8 + cg) * 4096;

    ms[tid] = (tid >= PAD && seq[b * SS + tid - PAD] > 0) ? 1.f : 0.f;
    int tb = PAD + slen[b] - 1;

    int t0 = tc * 32;
    bool live = (t0 <= tb);
    size_t base = ((size_t)b * LPAD + t0) * 512 + cg * 64 + 2 * c;
    float2 h[32];
    if (live) {
        #pragma unroll
        for (int j = 0; j < 32; j++)
            h[j] = __half22float2(*reinterpret_cast<const __half2*>(hh + base + (size_t)j * 512));
    } else {
        #pragma unroll
        for (int j = 0; j < 32; j++) h[j] = make_float2(0.f, 0.f);
    }
    __syncthreads();

    #pragma unroll
    for (int lev = 1; lev <= 5; lev++) {
        int half = 1 << (lev - 1);
        #pragma unroll
        for (int s = 0; s < 32; s += (1 << lev)) {
            int cpos = t0 + s + half - 1;
            if (ms[cpos] != 0.f) {
                float2 src = h[s + half - 1];
                #pragma unroll
                for (int p = 1; p <= (1 << (lev - 1)); p++) {
                    int j = s + half - 1 + p;
                    float lr = lamR[(p - 1) * 32 + c], liw = lamI[(p - 1) * 32 + c];
                    h[j].x += lr * src.x - liw * src.y;
                    h[j].y += lr * src.y + liw * src.x;
                }
            }
        }
    }

    bnd[tc][c] = h[31];
    __syncthreads();
    #pragma unroll
    for (int lev = 6; lev <= 8; lev++) {
        int l = 1 << lev, half = l >> 1;
        int blk = t0 >> lev;
        int cpos = blk * l + half - 1;
        if (live && t0 > cpos && ms[cpos] != 0.f) {
            float2 src = bnd[cpos >> 5][c];
            int p0 = t0 - cpos;
            #pragma unroll
            for (int j = 0; j < 32; j++) {
                int p = p0 + j;
                float lr = lamR[(p - 1) * 32 + c], liw = lamI[(p - 1) * 32 + c];
                h[j].x += lr * src.x - liw * src.y;
                h[j].y += lr * src.y + liw * src.x;
            }
            bnd[tc][c] = h[31];
        }
        __syncthreads();
    }

    if (live) {
        #pragma unroll
        for (int j = 0; j < 32; j++)
            *reinterpret_cast<__half2*>(hh + base + (size_t)j * 512) =
                __floats2half2_rn(h[j].x, h[j].y);
    }
}

// ============ low-register BN=64 fp16 GEMM, K=128 fixed, 3 CTAs/SM ==============
template<int EPI>
__global__ void __launch_bounds__(256, 3) hmma_gemm64(
        const fp16* __restrict__ A, const fp16* __restrict__ B,
        const float* __restrict__ bias, fp16* __restrict__ Ch,
        const int* __restrict__ lenp, int M, int N) {
    if (lenp && (blockIdx.y & 1) && lenp[blockIdx.y >> 1] < 73) return;

    char* sm = dyn_smem;
    float* sBias = (float*)sm;
    uint32_t sb = smem_u32(sm);
    int tid = threadIdx.x, lane = tid & 31, wid = tid >> 5;
    int q = lane & 3, hrow = lane >> 2;
    int wm = wid & 3, wn = wid >> 2;
    int m0 = blockIdx.y * 128, n0 = blockIdx.x * 64;

    #pragma unroll
    for (int c = 0; c < 2; c++) {
        uint32_t st = sb + SM_FIX + c * G2STAGE;
        int kc = c * 64;
        #pragma unroll
        for (int t = 0; t < 6; t++) {
            int idx = tid + t * 256;
            if (idx < 1024) {
                int row = idx >> 3, seg = idx & 7;
                cp_async16(st + row * GP + seg * 16,
                           A + (size_t)(m0 + row) * 128 + kc + seg * 8);
            } else {
                int r = idx - 1024;
                int row = r >> 3, seg = r & 7;
                cp_async16(st + G2A + row * GP + seg * 16,
                           B + (size_t)(n0 + row) * 128 + kc + seg * 8);
            }
        }
        asm volatile("cp.async.commit_group;");
    }
    if (tid < 64) sBias[tid] = bias[n0 + tid];

    float acc[2][4][4];
    #pragma unroll
    for (int a1 = 0; a1 < 2; a1++)
        #pragma unroll
        for (int a2 = 0; a2 < 4; a2++)
            #pragma unroll
            for (int a3 = 0; a3 < 4; a3++) acc[a1][a2][a3] = 0.f;

    #pragma unroll
    for (int ch = 0; ch < 2; ch++) {
        if (ch == 0) asm volatile("cp.async.wait_group 1;");
        else         asm volatile("cp.async.wait_group 0;");
        __syncthreads();
        uint32_t st = sb + SM_FIX + ch * G2STAGE;
        #pragma unroll
        for (int ks = 0; ks < 4; ks++) {
            uint32_t ah[2][4];
            #pragma unroll
            for (int mt = 0; mt < 2; mt++) {
                uint32_t aoff = (uint32_t)((wm*32 + mt*16 + (lane & 15)) * GP + ks*32 + (lane >> 4) * 16);
                ldsm4(ah[mt], st + aoff);
            }
            #pragma unroll
            for (int nb = 0; nb < 2; nb++) {
                uint32_t boff = (uint32_t)((wn*32 + nb*16 + (lane & 15)) * GP + ks*32 + (lane >> 4) * 16);
                uint32_t bh[4];
                ldsm4(bh, st + G2A + boff);
                #pragma unroll
                for (int mt = 0; mt < 2; mt++) {
                    mma16816(acc[mt][2*nb],   ah[mt], bh[0], bh[2]);
                    mma16816(acc[mt][2*nb+1], ah[mt], bh[1], bh[3]);
                }
            }
        }
    }

    #pragma unroll
    for (int mt = 0; mt < 2; mt++) {
        int r0 = m0 + wm*32 + mt*16 + hrow;
        #pragma unroll
        for (int j = 0; j < 4; j++) {
            int col = wn*32 + j*8 + q*2;
            float b0 = sBias[col], b1 = sBias[col+1];
            float v0 = acc[mt][j][0] + b0, v1 = acc[mt][j][1] + b1;
            float v2 = acc[mt][j][2] + b0, v3 = acc[mt][j][3] + b1;
            if (EPI == 1) {
                v0 = 0.5f * v0 * (1.f + erff(v0 * 0.70710678118654752f));
                v1 = 0.5f * v1 * (1.f + erff(v1 * 0.70710678118654752f));
                v2 = 0.5f * v2 * (1.f + erff(v2 * 0.70710678118654752f));
                v3 = 0.5f * v3 * (1.f + erff(v3 * 0.70710678118654752f));
            }
            packh2(v0, v1, Ch, (size_t)r0 * N + n0 + col);
            packh2(v2, v3, Ch, (size_t)(r0+8) * N + n0 + col);
        }
    }
}

// ================= fused FFN: gelu(x@W1^T+b1)@W2^T + b2 + x, then LN ============
// Block = 128 rows. 8 DFF-chunks of 64. x tile doubles as residual.
__global__ void __launch_bounds__(256, 2) ffn_fused(
        const fp16* __restrict__ X, const fp16* __restrict__ W1,
        const fp16* __restrict__ W2,
        const float* __restrict__ b1, const float* __restrict__ b2,
        const float* __restrict__ lng, const float* __restrict__ lnb,
        float* __restrict__ Cf, fp16* __restrict__ Ch,
        const int* __restrict__ lenp, int M) {
    if (lenp && (blockIdx.y & 1) && lenp[blockIdx.y >> 1] < 73) return;
    char* sm = dyn_smem;
    uint32_t sb = smem_u32(sm);
    float* sB1 = (float*)sm;                 // 512 floats
    float* sB2 = (float*)(sm + 2048);        // 128
    float* sG  = (float*)(sm + 2560);
    float* sBt = (float*)(sm + 3072);
    float* sred = (float*)(sm + F2_W1);      // overlay in epilogue
    int tid = threadIdx.x, lane = tid & 31, wid = tid >> 5;
    int q = lane & 3, hrow = lane >> 2;
    int wm = wid & 3, wn = wid >> 2;         // wn 0..1
    int m0 = blockIdx.y * 128;

    // x tile (both K-chunks of 64)
    #pragma unroll
    for (int t = 0; t < 8; t++) {
        int idx = tid + t * 256;             // 0..2047
        int row = idx >> 4, seg = idx & 15;
        int c = seg >> 3, s2 = seg & 7;
        cp_async16(sb + F2_X + c * 18432 + row * GP + s2 * 16,
                   X + (size_t)(m0 + row) * 128 + c * 64 + s2 * 8);
    }
    // w1[0]: 64 rows x 128 k (2 k-chunks)
    #pragma unroll
    for (int t = 0; t < 4; t++) {
        int idx = tid + t * 256;             // 0..1023
        int row = idx >> 4, seg = idx & 15;
        int c = seg >> 3, s2 = seg & 7;
        cp_async16(sb + F2_W1 + c * 9216 + row * GP + s2 * 16,
                   W1 + (size_t)row * 128 + c * 64 + s2 * 8);
    }
    // w2[0]: 128 rows x 64 k
    #pragma unroll
    for (int t = 0; t < 4; t++) {
        int idx = tid + t * 256;
        int row = idx >> 3, seg = idx & 7;
        cp_async16(sb + F2_W2 + row * GP + seg * 16,
                   W2 + (size_t)row * 512 + seg * 8);
    }
    asm volatile("cp.async.commit_group;");

    if (tid < 128) { sB2[tid] = b2[tid]; sG[tid] = lng[tid]; sBt[tid] = lnb[tid]; }
    for (int i = tid; i < 512; i += 256) sB1[i] = b1[i];

    float acc[2][8][4];
    #pragma unroll
    for (int a1 = 0; a1 < 2; a1++)
        #pragma unroll
        for (int a2 = 0; a2 < 8; a2++)
            #pragma unroll
            for (int a3 = 0; a3 < 4; a3++) acc[a1][a2][a3] = 0.f;

    for (int f = 0; f < 8; f++) {
        asm volatile("cp.async.wait_group 0;");
        __syncthreads();
        // GEMM1: hf[128x64] = x @ w1[f]^T  (warp tile 32x32)
        float acc1[2][4][4];
        #pragma unroll
        for (int a1 = 0; a1 < 2; a1++)
            #pragma unroll
            for (int a2 = 0; a2 < 4; a2++)
                #pragma unroll
                for (int a3 = 0; a3 < 4; a3++) acc1[a1][a2][a3] = 0.f;
        #pragma unroll
        for (int kc = 0; kc < 2; kc++) {
            uint32_t aX = sb + F2_X + kc * 18432;
            uint32_t aW = sb + F2_W1 + kc * 9216;
            #pragma unroll
            for (int ks = 0; ks < 4; ks++) {
                uint32_t ah[2][4];
                #pragma unroll
                for (int mt = 0; mt < 2; mt++) {
                    uint32_t aoff = (uint32_t)((wm*32 + mt*16 + (lane & 15)) * GP + ks*32 + (lane >> 4) * 16);
                    ldsm4(ah[mt], aX + aoff);
                }
                #pragma unroll
                for (int nb = 0; nb < 2; nb++) {
                    uint32_t boff = (uint32_t)((wn*32 + nb*16 + (lane & 15)) * GP + ks*32 + (lane >> 4) * 16);
                    uint32_t bh[4];
                    ldsm4(bh, aW + boff);
                    #pragma unroll
                    for (int mt = 0; mt < 2; mt++) {
                        mma16816(acc1[mt][2*nb],   ah[mt], bh[0], bh[2]);
                        mma16816(acc1[mt][2*nb+1], ah[mt], bh[1], bh[3]);
                    }
                }
            }
        }
        // gelu -> hf smem
        #pragma unroll
        for (int mt = 0; mt < 2; mt++) {
            int r0 = wm*32 + mt*16 + hrow;
            #pragma unroll
            for (int j = 0; j < 4; j++) {
                int col = wn*32 + j*8 + q*2;
                float bb0 = sB1[f*64 + col], bb1 = sB1[f*64 + col + 1];
                float v0 = acc1[mt][j][0] + bb0, v1 = acc1[mt][j][1] + bb1;
                float v2 = acc1[mt][j][2] + bb0, v3 = acc1[mt][j][3] + bb1;
                v0 = 0.5f * v0 * (1.f + erff(v0 * 0.70710678118654752f));
                v1 = 0.5f * v1 * (1.f + erff(v1 * 0.70710678118654752f));
                v2 = 0.5f * v2 * (1.f + erff(v2 * 0.70710678118654752f));
                v3 = 0.5f * v3 * (1.f + erff(v3 * 0.70710678118654752f));
                *(__half2*)(sm + F2_HF + r0 * GP + col * 2)       = __floats2half2_rn(v0, v1);
                *(__half2*)(sm + F2_HF + (r0 + 8) * GP + col * 2) = __floats2half2_rn(v2, v3);
            }
        }
        __syncthreads();      // hf visible; w1 free
        if (f + 1 < 8) {
            const fp16* W1n = W1 + (size_t)(f + 1) * 64 * 128;
            #pragma unroll
            for (int t = 0; t < 4; t++) {
                int idx = tid + t * 256;
                int row = idx >> 4, seg = idx & 15;
                int c = seg >> 3, s2 = seg & 7;
                cp_async16(sb + F2_W1 + c * 9216 + row * GP + s2 * 16,
                           W1n + (size_t)row * 128 + c * 64 + s2 * 8);
            }
        }
        asm volatile("cp.async.commit_group;");
        // GEMM2: acc += hf @ w2[f]^T  (warp tile 32x64, K=64)
        #pragma unroll
        for (int ks = 0; ks < 4; ks++) {
            uint32_t ah[2][4];
            #pragma unroll
            for (int mt = 0; mt < 2; mt++) {
                uint32_t aoff = (uint32_t)((wm*32 + mt*16 + (lane & 15)) * GP + ks*32 + (lane >> 4) * 16);
                ldsm4(ah[mt], sb + F2_HF + aoff);
            }
            #pragma unroll
            for (int nb = 0; nb < 4; nb++) {
                uint32_t boff = (uint32_t)((wn*64 + nb*16 + (lane & 15)) * GP + ks*32 + (lane >> 4) * 16);
                uint32_t bh[4];
                ldsm4(bh, sb + F2_W2 + boff);
                #pragma unroll
                for (int mt = 0; mt < 2; mt++) {
                    mma16816(acc[mt][2*nb],   ah[mt], bh[0], bh[2]);
                    mma16816(acc[mt][2*nb+1], ah[mt], bh[1], bh[3]);
                }
            }
        }
        __syncthreads();      // hf + w2 free
        if (f + 1 < 8) {
            const fp16* W2n = W2 + (size_t)(f + 1) * 64;
            #pragma unroll
            for (int t = 0; t < 4; t++) {
                int idx = tid + t * 256;
                int row = idx >> 3, seg = idx & 7;
                cp_async16(sb + F2_W2 + row * GP + seg * 16,
                           W2n + (size_t)row * 512 + seg * 8);
            }
        }
        asm volatile("cp.async.commit_group;");
    }

    // ---------------- epilogue: bias2 + residual(x, from smem) + LN ----------------
    float mu[2][2], rs[2][2];
    #pragma unroll
    for (int mt = 0; mt < 2; mt++) {
        int rl = wm*32 + mt*16 + hrow;
        #pragma unroll
        for (int j = 0; j < 8; j++) {
            int col = wn*64 + j*8 + q*2;
            float b0 = sB2[col], b1v = sB2[col+1];
            uint32_t xoff = (uint32_t)(F2_X + wn * 18432 + (j*8 + q*2) * 2);
            float2 ra = __half22float2(*(const __half2*)(sm + xoff + rl * GP));
            float2 rb = __half22float2(*(const __half2*)(sm + xoff + (rl + 8) * GP));
            acc[mt][j][0] += b0 + ra.x;  acc[mt][j][1] += b1v + ra.y;
            acc[mt][j][2] += b0 + rb.x;  acc[mt][j][3] += b1v + rb.y;
        }
    }
    float ssum[2][2] = {{0,0},{0,0}}, ssq[2][2] = {{0,0},{0,0}};
    #pragma unroll
    for (int mt = 0; mt < 2; mt++)
        #pragma unroll
        for (int j = 0; j < 8; j++)
            #pragma unroll
            for (int hh = 0; hh < 2; hh++) {
                float v0 = acc[mt][j][2*hh], v1 = acc[mt][j][2*hh+1];
                ssum[mt][hh] += v0 + v1;
                ssq[mt][hh]  += v0*v0 + v1*v1;
            }
    #pragma unroll
    for (int mt = 0; mt < 2; mt++)
        #pragma unroll
        for (int hh = 0; hh < 2; hh++) {
            ssum[mt][hh] += __shfl_xor_sync(0xffffffffu, ssum[mt][hh], 1);
            ssum[mt][hh] += __shfl_xor_sync(0xffffffffu, ssum[mt][hh], 2);
            ssq[mt][hh]  += __shfl_xor_sync(0xffffffffu, ssq[mt][hh], 1);
            ssq[mt][hh]  += __shfl_xor_sync(0xffffffffu, ssq[mt][hh], 2);
        }
    if (q == 0) {
        #pragma unroll
        for (int mt = 0; mt < 2; mt++)
            #pragma unroll
            for (int hh = 0; hh < 2; hh++) {
                int lr = wm*32 + mt*16 + hrow + hh*8;
                sred[lr*2 + wn]       = ssum[mt][hh];
                sred[256 + lr*2 + wn] = ssq[mt][hh];
            }
    }
    __syncthreads();
    #pragma unroll
    for (int mt = 0; mt < 2; mt++)
        #pragma unroll
        for (int hh = 0; hh < 2; hh++) {
            int lr = wm*32 + mt*16 + hrow + hh*8;
            float S  = sred[lr*2] + sred[lr*2 + 1];
            float S2 = sred[256 + lr*2] + sred[256 + lr*2 + 1];
            float m  = S * (1.f/128.f);
            float var = S2 * (1.f/128.f) - m * m;
            mu[mt][hh] = m;
            rs[mt][hh] = rsqrtf(var + 1e-5f);
        }
    #pragma unroll
    for (int mt = 0; mt < 2; mt++) {
        int r0 = m0 + wm*32 + mt*16 + hrow;
        #pragma unroll
        for (int j = 0; j < 8; j++) {
            int col = wn*64 + j*8 + q*2;
            float g0 = sG[col], g1 = sG[col+1], bb0 = sBt[col], bb1 = sBt[col+1];
            float v0 = (acc[mt][j][0] - mu[mt][0]) * rs[mt][0] * g0 + bb0;
            float v1 = (acc[mt][j][1] - mu[mt][0]) * rs[mt][0] * g1 + bb1;
            float v2 = (acc[mt][j][2] - mu[mt][1]) * rs[mt][1] * g0 + bb0;
            float v3 = (acc[mt][j][3] - mu[mt][1]) * rs[mt][1] * g1 + bb1;
            if (Cf) {
                *(float2*)(Cf + (size_t)r0 * 128 + col)     = make_float2(v0, v1);
                *(float2*)(Cf + (size_t)(r0+8) * 128 + col) = make_float2(v2, v3);
            }
            if (Ch) {
                packh2(v0, v1, Ch, (size_t)r0 * 128 + col);
                packh2(v2, v3, Ch, (size_t)(r0+8) * 128 + col);
            }
        }
    }
}

// ================= pipelined fp16 GEMM BN=128 (K=512: out-projection) ===========
__device__ __forceinline__ void gemm_load_chunk(
        uint32_t st, const fp16* A, const fp16* B,
        int m0, int n0, int kc, int K, int tid) {
    #pragma unroll
    for (int t = 0; t < 4; t++) {
        int idx = tid + t * 256;
        int row = idx >> 3, seg = idx & 7;
        uint32_t so = row * GP + seg * 16;
        cp_async16(st + so,         A + (size_t)(m0 + row) * K + kc + seg * 8);
        cp_async16(st + GTILE + so, B + (size_t)(n0 + row) * K + kc + seg * 8);
    }
}

template<int EPI>
__global__ void __launch_bounds__(256, 2) hmma_gemm(
        const fp16* __restrict__ A, const fp16* __restrict__ B,
        const float* __restrict__ bias, const fp16* __restrict__ Res,
        const float* __restrict__ lng, const float* __restrict__ lnb,
        float* __restrict__ Cf, fp16* __restrict__ Ch,
        const int* __restrict__ lenp,
        int M, int N, int K) {
    if (lenp && (blockIdx.y & 1) && lenp[blockIdx.y >> 1] < 73) return;

    char* sm = dyn_smem;
    float* sBias = (float*)sm;
    float* sG    = sBias + 128;
    float* sB    = sG + 128;
    float* sred  = (float*)(sm + SM_FIX);
    uint32_t sb = smem_u32(sm);

    int tid = threadIdx.x, lane = tid & 31, wid = tid >> 5;
    int q = lane & 3, hrow = lane >> 2;
    int wm = wid & 3, wn = wid >> 2;
    int m0 = blockIdx.y * 128, n0 = blockIdx.x * 128;

    if (tid < 128) {
        sBias[tid] = bias[n0 + tid];
        if (EPI == 2) { sG[tid] = lng[n0 + tid]; sB[tid] = lnb[n0 + tid]; }
    }

    float acc[2][8][4];
    #pragma unroll
    for (int a1 = 0; a1 < 2; a1++)
        #pragma unroll
        for (int a2 = 0; a2 < 8; a2++)
            #pragma unroll
            for (int a3 = 0; a3 < 4; a3++) acc[a1][a2][a3] = 0.f;

    int nc = K >> 6;
    gemm_load_chunk(sb + SM_FIX, A, B, m0, n0, 0, K, tid);
    asm volatile("cp.async.commit_group;");
    if (nc > 1) gemm_load_chunk(sb + SM_FIX + GSTAGE, A, B, m0, n0, 64, K, tid);
    asm volatile("cp.async.commit_group;");

    for (int ch = 0; ch < nc; ch++) {
        asm volatile("cp.async.wait_group 1;");
        __syncthreads();
        uint32_t st = sb + SM_FIX + (ch % NSTAGE) * GSTAGE;
        uint32_t aA = st, aB = st + GTILE;
        #pragma unroll
        for (int ks = 0; ks < 4; ks++) {
            uint32_t ah[2][4];
            #pragma unroll
            for (int mt = 0; mt < 2; mt++) {
                uint32_t aoff = (uint32_t)((wm*32 + mt*16 + (lane & 15)) * GP + ks*32 + (lane >> 4) * 16);
                ldsm4(ah[mt], aA + aoff);
            }
            #pragma unroll
            for (int nb = 0; nb < 4; nb++) {
                uint32_t boff = (uint32_t)((wn*64 + nb*16 + (lane & 15)) * GP + ks*32 + (lane >> 4) * 16);
                uint32_t bh[4];
                ldsm4(bh, aB + boff);
                #pragma unroll
                for (int mt = 0; mt < 2; mt++) {
                    mma16816(acc[mt][2*nb],   ah[mt], bh[0], bh[2]);
                    mma16816(acc[mt][2*nb+1], ah[mt], bh[1], bh[3]);
                }
            }
        }
        if (ch + 2 < nc)
            gemm_load_chunk(sb + SM_FIX + ((ch + 2) % NSTAGE) * GSTAGE,
                            A, B, m0, n0, (ch + 2) << 6, K, tid);
        asm volatile("cp.async.commit_group;");
    }
    __syncthreads();

    #pragma unroll
    for (int mt = 0; mt < 2; mt++)
        #pragma unroll
        for (int j = 0; j < 8; j++) {
            int col = wn*64 + j*8 + q*2;
            float b0 = sBias[col], b1 = sBias[col+1];
            acc[mt][j][0] += b0; acc[mt][j][1] += b1;
            acc[mt][j][2] += b0; acc[mt][j][3] += b1;
        }
    if (EPI == 1) {
        #pragma unroll
        for (int mt = 0; mt < 2; mt++)
            #pragma unroll
            for (int j = 0; j < 8; j++)
                #pragma unroll
                for (int v = 0; v < 4; v++)
                    acc[mt][j][v] = 0.5f * acc[mt][j][v] *
                                    (1.f + erff(acc[mt][j][v] * 0.70710678118654752f));
    }
    if (EPI == 2) {
        float mu[2][2], rs[2][2];
        #pragma unroll
        for (int mt = 0; mt < 2; mt++) {
            int r0 = m0 + wm*32 + mt*16 + hrow;
            #pragma unroll
            for (int j = 0; j < 8; j++) {
                int col = wn*64 + j*8 + q*2;
                float2 ra = __half22float2(*(const __half2*)(Res + (size_t)r0 * 128 + col));
                float2 rb = __half22float2(*(const __half2*)(Res + (size_t)(r0+8) * 128 + col));
                acc[mt][j][0] += ra.x; acc[mt][j][1] += ra.y;
                acc[mt][j][2] += rb.x; acc[mt][j][3] += rb.y;
            }
        }
        float ssum[2][2] = {{0,0},{0,0}}, ssq[2][2] = {{0,0},{0,0}};
        #pragma unroll
        for (int mt = 0; mt < 2; mt++)
            #pragma unroll
            for (int j = 0; j < 8; j++)
                #pragma unroll
                for (int hh = 0; hh < 2; hh++) {
                    float v0 = acc[mt][j][2*hh], v1 = acc[mt][j][2*hh+1];
                    ssum[mt][hh] += v0 + v1;
                    ssq[mt][hh]  += v0*v0 + v1*v1;
                }
        #pragma unroll
        for (int mt = 0; mt < 2; mt++)
            #pragma unroll
            for (int hh = 0; hh < 2; hh++) {
                ssum[mt][hh] += __shfl_xor_sync(0xffffffffu, ssum[mt][hh], 1);
                ssum[mt][hh] += __shfl_xor_sync(0xffffffffu, ssum[mt][hh], 2);
                ssq[mt][hh]  += __shfl_xor_sync(0xffffffffu, ssq[mt][hh], 1);
                ssq[mt][hh]  += __shfl_xor_sync(0xffffffffu, ssq[mt][hh], 2);
            }
        if (q == 0) {
            #pragma unroll
            for (int mt = 0; mt < 2; mt++)
                #pragma unroll
                for (int hh = 0; hh < 2; hh++) {
                    int lr = wm*32 + mt*16 + hrow + hh*8;
                    sred[lr*2 + wn]       = ssum[mt][hh];
                    sred[256 + lr*2 + wn] = ssq[mt][hh];
                }
        }
        __syncthreads();
        #pragma unroll
        for (int mt = 0; mt < 2; mt++)
            #pragma unroll
            for (int hh = 0; hh < 2; hh++) {
                int lr = wm*32 + mt*16 + hrow + hh*8;
                float S  = sred[lr*2] + sred[lr*2 + 1];
                float S2 = sred[256 + lr*2] + sred[256 + lr*2 + 1];
                float m  = S * (1.f/128.f);
                float var = S2 * (1.f/128.f) - m * m;
                mu[mt][hh] = m;
                rs[mt][hh] = rsqrtf(var + 1e-5f);
            }
        #pragma unroll
        for (int mt = 0; mt < 2; mt++)
            #pragma unroll
            for (int j = 0; j < 8; j++) {
                int col = wn*64 + j*8 + q*2;
                float g0 = sG[col], g1 = sG[col+1], bb0 = sB[col], bb1 = sB[col+1];
                acc[mt][j][0] = (acc[mt][j][0] - mu[mt][0]) * rs[mt][0] * g0 + bb0;
                acc[mt][j][1] = (acc[mt][j][1] - mu[mt][0]) * rs[mt][0] * g1 + bb1;
                acc[mt][j][2] = (acc[mt][j][2] - mu[mt][1]) * rs[mt][1] * g0 + bb0;
                acc[mt][j][3] = (acc[mt][j][3] - mu[mt][1]) * rs[mt][1] * g1 + bb1;
            }
    }
    #pragma unroll
    for (int mt = 0; mt < 2; mt++) {
        int r0 = m0 + wm*32 + mt*16 + hrow;
        #pragma unroll
        for (int j = 0; j < 8; j++) {
            int col = n0 + wn*64 + j*8 + q*2;
            if (Cf) {
                *(float2*)(Cf + (size_t)r0 * N + col)     = make_float2(acc[mt][j][0], acc[mt][j][1]);
                *(float2*)(Cf + (size_t)(r0+8) * N + col) = make_float2(acc[mt][j][2], acc[mt][j][3]);
            }
            if (Ch) {
                packh2(acc[mt][j][0], acc[mt][j][1], Ch, (size_t)r0 * N + col);
                packh2(acc[mt][j][2], acc[mt][j][3], Ch, (size_t)(r0+8) * N + col);
            }
        }
    }
}

// ---------------- host driver ---------------------------------------------------
extern "C" void kernel_launch(void* const* d_in, const int* in_sizes, int n_in,
                              void* d_out, int out_size) {
    const float* token_emb  = (const float*)d_in[0];
    const float* emb_ln_g   = (const float*)d_in[1];
    const float* emb_ln_b   = (const float*)d_in[2];
    const float* params_log = (const float*)d_in[3];
    const float* in_wr      = (const float*)d_in[4];
    const float* in_wi      = (const float*)d_in[5];
    const float* in_br      = (const float*)d_in[6];
    const float* in_bi      = (const float*)d_in[7];
    const float* out_wr     = (const float*)d_in[8];
    const float* out_wi     = (const float*)d_in[9];
    const float* out_br     = (const float*)d_in[10];
    const float* lru_ln_g   = (const float*)d_in[12];
    const float* lru_ln_b   = (const float*)d_in[13];
    const float* w1         = (const float*)d_in[14];
    const float* b1         = (const float*)d_in[15];
    const float* w2         = (const float*)d_in[16];
    const float* b2         = (const float*)d_in[17];
    const float* ffn_ln_g   = (const float*)d_in[18];
    const float* ffn_ln_b   = (const float*)d_in[19];
    const int*   item_seq   = (const int*)d_in[20];
    const int*   item_len   = (const int*)d_in[21];
    float* out = (float*)d_out;

    float *pbin;
    fp16 *pxh, *px2h, *phh, *pWin, *pWout, *pw1, *pw2;
    fp16 *psm1h, *phgh, *pxgh;
    cudaGetSymbolAddress((void**)&pxh,   g_xh);
    cudaGetSymbolAddress((void**)&px2h,  g_x2h);
    cudaGetSymbolAddress((void**)&phh,   g_hh);
    cudaGetSymbolAddress((void**)&pWin,  g_Win);
    cudaGetSymbolAddress((void**)&pbin,  g_bin);
    cudaGetSymbolAddress((void**)&pWout, g_Wout);
    cudaGetSymbolAddress((void**)&pw1,   g_w1);
    cudaGetSymbolAddress((void**)&pw2,   g_w2);
    cudaGetSymbolAddress((void**)&pxgh,  g_xgh);
    cudaGetSymbolAddress((void**)&psm1h, g_sm1h);
    cudaGetSymbolAddress((void**)&phgh,  g_hgh);

    cudaFuncSetAttribute(hmma_gemm<2>, cudaFuncAttributeMaxDynamicSharedMemorySize, GSM_TOT);
    cudaFuncSetAttribute(hmma_gemm64<0>, cudaFuncAttributeMaxDynamicSharedMemorySize, G2SM);
    cudaFuncSetAttribute(ffn_fused, cudaFuncAttributeMaxDynamicSharedMemorySize, F2_SM);

    for (int li = 0; li < NLAY; li++) {
        pack_kernel<<<1024, 256>>>(in_wr, in_wi, in_br, in_bi, out_wr, out_wi,
                                   w1, w2, params_log, li);
        lam_kernel<<<128, 256>>>(params_log, li);
    }
    embed_kernel<<<MTOK/8, 256>>>(token_emb, emb_ln_g, emb_ln_b, item_seq, pxh);

    for (int li = 0; li < NLAY; li++) {
        hmma_gemm64<0><<<dim3(8, MTOK/128), 256, G2SM>>>(
            pxh, pWin + (size_t)li * 2*DH*DD, pbin + li * 2*DH,
            phh, item_len, MTOK, 512);
        scan_kernel<<<dim3(8, BB), 256>>>(phh, item_seq, item_len, li);

        if (li == 0) {
            hmma_gemm<2><<<dim3(1, MTOK/128), 256, GSM_TOT>>>(
                phh, pWout + (size_t)li * DD*2*DH, out_br + li*DD, pxh,
                lru_ln_g + li*DD, lru_ln_b + li*DD,
                nullptr, px2h, item_len, MTOK, 128, 512);
            ffn_fused<<<dim3(1, MTOK/128), 256, F2_SM>>>(
                px2h, pw1 + (size_t)li * DFF*DD, pw2 + (size_t)li * DD*DFF,
                b1 + li*DFF, b2 + li*DD, ffn_ln_g + li*DD, ffn_ln_b + li*DD,
                nullptr, pxh, item_len, MTOK);
        } else {
            gather_kernel<<<BB, 512>>>(phh, pxh, item_len, phgh, pxgh);
            hmma_gemm<2><<<dim3(1, BB/128), 256, GSM_TOT>>>(
                phgh, pWout + (size_t)li * DD*2*DH, out_br + li*DD, pxgh,
                lru_ln_g + li*DD, lru_ln_b + li*DD,
                nullptr, psm1h, nullptr, BB, 128, 512);
            ffn_fused<<<dim3(1, BB/128), 256, F2_SM>>>(
                psm1h, pw1 + (size_t)li * DFF*DD, pw2 + (size_t)li * DD*DFF,
                b1 + li*DFF, b2 + li*DD, ffn_ln_g + li*DD, ffn_ln_b + li*DD,
                out, nullptr, nullptr, BB);
        }
    }
}

// round 16
// speedup vs baseline: 1.4771x; 1.3046x over previous
#include <cuda_runtime.h>
#include <cuda_bf16.h>
#include <cuda_fp16.h>
#include <math.h>
#include <stdint.h>

// Problem constants
#define BB   512
#define SS   200
#define DD   128
#define NLAY 2
#define DH   256      // complex hidden (512 reals)
#define DFF  512
#define LPAD 256
#define PAD  56
#define MTOK (BB*LPAD)
#define MAXR (BB*SS)          // 102400 max live rows
#define MAXT (MAXR/128)       // 800 row-tiles

typedef __half fp16;

// single dynamic-smem symbol shared by all kernels
extern __shared__ __align__(16) char dyn_smem[];

// ---------------- scratch (device globals) ------------------------------------
__device__ fp16 g_xc [MAXR * DD];     // compacted x
__device__ fp16 g_x2c[MAXR * DD];     // compacted x2
__device__ fp16 g_hh [MTOK * 2*DH];   // padded h (scan layout)
__device__ int  g_off[BB + 1];
__device__ int  g_nrows;
__device__ int  g_map[MAXR];          // compact row -> padded token index
// packed weights for BOTH layers + lambda tables
__device__ fp16 g_Win[NLAY*2*DH*DD];
__device__ float g_bin[NLAY*2*DH];
__device__ fp16 g_Wout[NLAY*DD*2*DH];
__device__ fp16 g_w1[NLAY*DFF*DD];
__device__ fp16 g_w2[NLAY*DD*DFF];
__device__ float g_lamR[NLAY*8*128*32];
__device__ float g_lamI[NLAY*8*128*32];
// layer-2 tail (gathered, M=BB)
__device__ fp16 g_xgh[BB * DD];
__device__ fp16 g_sm1h[BB*DD];
__device__ fp16 g_hgh[BB*2*DH];

// ---------------- helpers -------------------------------------------------------
__device__ __forceinline__ uint32_t smem_u32(const void* p) {
    uint32_t a;
    asm("{ .reg .u64 t; cvta.to.shared.u64 t, %1; cvt.u32.u64 %0, t; }" : "=r"(a) : "l"(p));
    return a;
}
__device__ __forceinline__ void cp_async16(uint32_t s, const void* g) {
    asm volatile("cp.async.cg.shared.global [%0], [%1], 16;" :: "r"(s), "l"(g));
}
__device__ __forceinline__ void ldsm4(uint32_t (&r)[4], uint32_t addr) {
    asm volatile("ldmatrix.sync.aligned.m8n8.x4.shared.b16 {%0,%1,%2,%3}, [%4];"
                 : "=r"(r[0]), "=r"(r[1]), "=r"(r[2]), "=r"(r[3]) : "r"(addr));
}
__device__ __forceinline__ void mma16816(float* c, const uint32_t* a, uint32_t b0, uint32_t b1) {
    asm volatile("mma.sync.aligned.m16n8k16.row.col.f32.f16.f16.f32 "
                 "{%0,%1,%2,%3}, {%4,%5,%6,%7}, {%8,%9}, {%0,%1,%2,%3};"
                 : "+f"(c[0]), "+f"(c[1]), "+f"(c[2]), "+f"(c[3])
                 : "r"(a[0]), "r"(a[1]), "r"(a[2]), "r"(a[3]), "r"(b0), "r"(b1));
}
__device__ __forceinline__ void packh2(float a, float b, fp16* H, size_t idx) {
    *reinterpret_cast<__half2*>(H + idx) = __floats2half2_rn(a, b);
}

#define SM_FIX 1536
#define GP     144
#define GTILE  (128*GP)
#define GSTAGE (2*GTILE)
#define NSTAGE 3
#define GSM_TOT (SM_FIX + NSTAGE*GSTAGE)   // 112128 -> 2 CTAs/SM

// low-register BN=64 variant (K=128)
#define G2A     (128*GP)
#define G2B     (64*GP)
#define G2STAGE (G2A + G2B)
#define G2SM    (SM_FIX + 2*G2STAGE)       // 56832 -> 3 CTAs/SM

// fused FFN
#define F2_FIX 3584
#define F2_X   F2_FIX
#define F2_W1  (F2_FIX + 36864)
#define F2_HF  (F2_W1 + 18432)
#define F2_W2  (F2_HF + 18432)
#define F2_SM  (F2_W2 + 18432)             // 95744 -> 2 CTAs/SM

// ---------------- prefix sum of lengths ----------------------------------------
__global__ void prefix_kernel(const int* __restrict__ slen) {
    __shared__ int s[512];
    int tid = threadIdx.x;
    int v0 = slen[tid];
    s[tid] = v0;
    __syncthreads();
    for (int o = 1; o < 512; o <<= 1) {
        int v = (tid >= o) ? s[tid - o] : 0;
        __syncthreads();
        s[tid] += v;
        __syncthreads();
    }
    g_off[tid] = s[tid] - v0;
    if (tid == 511) { g_off[512] = s[511]; g_nrows = s[511]; }
}

// map tail: dead rows scatter to padded index 0 (masked padding, never read)
__global__ void maptail_kernel() {
    int idx = blockIdx.x * 256 + threadIdx.x;
    if (idx < MAXR && idx >= g_nrows) g_map[idx] = 0;
}

// ---------------- embedding gather + LN (warp per live token, compact out) ------
__global__ void embed_kernel(const float* __restrict__ emb,
                             const float* __restrict__ g,
                             const float* __restrict__ bta,
                             const int*   __restrict__ seq,
                             const int*   __restrict__ slen,
                             fp16* __restrict__ xc) {
    int gidx = blockIdx.x * 8 + (threadIdx.x >> 5);   // 0..102399
    int lane = threadIdx.x & 31;
    int b = gidx / SS, j = gidx - b * SS;
    if (j >= slen[b]) return;
    int row = g_off[b] + j;
    int item = seq[b * SS + j];
    float4 v = *reinterpret_cast<const float4*>(emb + (size_t)item * DD + lane * 4);
    float s = v.x + v.y + v.z + v.w;
    #pragma unroll
    for (int off = 16; off > 0; off >>= 1) s += __shfl_xor_sync(0xffffffffu, s, off);
    float mu = s * (1.f / DD);
    float dx = v.x - mu, dy = v.y - mu, dz = v.z - mu, dw = v.w - mu;
    float qq = dx*dx + dy*dy + dz*dz + dw*dw;
    #pragma unroll
    for (int off = 16; off > 0; off >>= 1) qq += __shfl_xor_sync(0xffffffffu, qq, off);
    float rs = rsqrtf(qq * (1.f / DD) + 1e-5f);
    float4 gg = *reinterpret_cast<const float4*>(g + lane * 4);
    float4 bb = *reinterpret_cast<const float4*>(bta + lane * 4);
    __half2 h01 = __floats2half2_rn(dx * rs * gg.x + bb.x, dy * rs * gg.y + bb.y);
    __half2 h23 = __floats2half2_rn(dz * rs * gg.z + bb.z, dw * rs * gg.w + bb.w);
    uint2 pk;
    pk.x = *reinterpret_cast<uint32_t*>(&h01);
    pk.y = *reinterpret_cast<uint32_t*>(&h23);
    *reinterpret_cast<uint2*>(&xc[(size_t)row * DD + lane * 4]) = pk;
    if (lane == 0) g_map[row] = b * LPAD + PAD + j;
}

// ---------------- lambda-power table --------------------------------------------
__global__ void lam_kernel(const float* __restrict__ params_log, int li) {
    int idx = blockIdx.x * 256 + threadIdx.x;
    int cg = idx >> 12, rem = idx & 4095;
    int p = (rem >> 5) + 1, c = rem & 31;
    int d = cg * 32 + c;
    float nu = expf(params_log[(li * 3 + 0) * DH + d]);
    float th = expf(params_log[(li * 3 + 1) * DH + d]);
    float mag = expf(-nu * (float)p);
    float sv, cv;
    sincosf(th * (float)p, &sv, &cv);
    g_lamR[li * 32768 + idx] = mag * cv;
    g_lamI[li * 32768 + idx] = mag * sv;
}

// ---------------- weight packing -------------------------------------------------
__global__ void pack_kernel(const float* __restrict__ in_wr, const float* __restrict__ in_wi,
                            const float* __restrict__ in_br, const float* __restrict__ in_bi,
                            const float* __restrict__ out_wr, const float* __restrict__ out_wi,
                            const float* __restrict__ w1, const float* __restrict__ w2,
                            const float* __restrict__ params_log, int li) {
    int idx = blockIdx.x * 256 + threadIdx.x;
    int mat = idx >> 16, r = idx & 65535;
    float w;
    fp16* Dst;
    if (mat == 0) {
        int n = r >> 7, k = r & 127;
        int d = n >> 1, s = n & 1;
        float gamma = expf(params_log[(li * 3 + 2) * DH + d]);
        w = (s ? in_wi[(size_t)li * DH * DD + d * DD + k]
               : in_wr[(size_t)li * DH * DD + d * DD + k]) * gamma;
        if (k == 0) {
            float bv = s ? in_bi[li * DH + d] : in_br[li * DH + d];
            g_bin[li * 2*DH + n] = bv * gamma;
        }
        Dst = g_Win + (size_t)li * 2*DH*DD;
    } else if (mat == 1) {
        int n = r >> 9, k = r & 511;
        int d = k >> 1, s = k & 1;
        w = s ? -out_wi[(size_t)li * DD * DH + n * DH + d]
              :  out_wr[(size_t)li * DD * DH + n * DH + d];
        Dst = g_Wout + (size_t)li * DD*2*DH;
    } else if (mat == 2) {
        w = w1[(size_t)li * DFF * DD + r];
        Dst = g_w1 + (size_t)li * DFF*DD;
    } else {
        w = w2[(size_t)li * DD * DFF + r];
        Dst = g_w2 + (size_t)li * DD*DFF;
    }
    Dst[r] = __float2half_rn(w);
}

// ---------------- gather last valid token --------------------------------------
__global__ void gather_kernel(const fp16* __restrict__ hh,
                              const fp16* __restrict__ xc, const int* __restrict__ slen,
                              fp16* __restrict__ hgh, fp16* __restrict__ xgh) {
    int b = blockIdx.x, tid = threadIdx.x;
    int len = slen[b];
    int t = PAD + len - 1;
    hgh[(size_t)b * 512 + tid] = hh[((size_t)b * LPAD + t) * 512 + tid];
    if (tid < DD) xgh[(size_t)b * DD + tid] = xc[(size_t)(g_off[b] + len - 1) * DD + tid];
}

// ================= register-resident masked LRU tree scan (padded layout) =======
__global__ void __launch_bounds__(256) scan_kernel(fp16* __restrict__ hh,
                                                   const int* __restrict__ seq,
                                                   const int* __restrict__ slen, int li) {
    __shared__ float ms[LPAD];
    __shared__ float2 bnd[8][32];
    int b = blockIdx.y, cg = blockIdx.x;
    int tid = threadIdx.x;
    int c = tid & 31, tc = tid >> 5;
    const float* lamR = g_lamR + ((size_t)li * 8 + cg) * 4096;
    const float* lamI = g_lamI + ((size_t)li * 8 + cg) * 4096;

    ms[tid] = (tid >= PAD && seq[b * SS + tid - PAD] > 0) ? 1.f : 0.f;
    int tb = PAD + slen[b] - 1;

    int t0 = tc * 32;
    bool live = (t0 <= tb);
    size_t base = ((size_t)b * LPAD + t0) * 512 + cg * 64 + 2 * c;
    float2 h[32];
    if (live) {
        #pragma unroll
        for (int j = 0; j < 32; j++)
            h[j] = __half22float2(*reinterpret_cast<const __half2*>(hh + base + (size_t)j * 512));
    } else {
        #pragma unroll
        for (int j = 0; j < 32; j++) h[j] = make_float2(0.f, 0.f);
    }
    __syncthreads();

    #pragma unroll
    for (int lev = 1; lev <= 5; lev++) {
        int half = 1 << (lev - 1);
        #pragma unroll
        for (int s = 0; s < 32; s += (1 << lev)) {
            int cpos = t0 + s + half - 1;
            if (ms[cpos] != 0.f) {
                float2 src = h[s + half - 1];
                #pragma unroll
                for (int p = 1; p <= (1 << (lev - 1)); p++) {
                    int j = s + half - 1 + p;
                    float lr = lamR[(p - 1) * 32 + c], liw = lamI[(p - 1) * 32 + c];
                    h[j].x += lr * src.x - liw * src.y;
                    h[j].y += lr * src.y + liw * src.x;
                }
            }
        }
    }

    bnd[tc][c] = h[31];
    __syncthreads();
    #pragma unroll
    for (int lev = 6; lev <= 8; lev++) {
        int l = 1 << lev, half = l >> 1;
        int blk = t0 >> lev;
        int cpos = blk * l + half - 1;
        if (live && t0 > cpos && ms[cpos] != 0.f) {
            float2 src = bnd[cpos >> 5][c];
            int p0 = t0 - cpos;
            #pragma unroll
            for (int j = 0; j < 32; j++) {
                int p = p0 + j;
                float lr = lamR[(p - 1) * 32 + c], liw = lamI[(p - 1) * 32 + c];
                h[j].x += lr * src.x - liw * src.y;
                h[j].y += lr * src.y + liw * src.x;
            }
            bnd[tc][c] = h[31];
        }
        __syncthreads();
    }

    if (live) {
        #pragma unroll
        for (int j = 0; j < 32; j++)
            *reinterpret_cast<__half2*>(hh + base + (size_t)j * 512) =
                __floats2half2_rn(h[j].x, h[j].y);
    }
}

// ============ in-projection: BN=64 fp16 GEMM K=128, compact in, scatter out =====
__global__ void __launch_bounds__(256, 3) hmma_gemm64(
        const fp16* __restrict__ A, const fp16* __restrict__ B,
        const float* __restrict__ bias, fp16* __restrict__ Ch,
        int N) {
    int m0 = blockIdx.y * 128;
    if (m0 >= g_nrows) return;

    char* sm = dyn_smem;
    float* sBias = (float*)sm;
    uint32_t sb = smem_u32(sm);
    int tid = threadIdx.x, lane = tid & 31, wid = tid >> 5;
    int q = lane & 3, hrow = lane >> 2;
    int wm = wid & 3, wn = wid >> 2;
    int n0 = blockIdx.x * 64;

    #pragma unroll
    for (int c = 0; c < 2; c++) {
        uint32_t st = sb + SM_FIX + c * G2STAGE;
        int kc = c * 64;
        #pragma unroll
        for (int t = 0; t < 6; t++) {
            int idx = tid + t * 256;
            if (idx < 1024) {
                int row = idx >> 3, seg = idx & 7;
                cp_async16(st + row * GP + seg * 16,
                           A + (size_t)(m0 + row) * 128 + kc + seg * 8);
            } else {
                int r = idx - 1024;
                int row = r >> 3, seg = r & 7;
                cp_async16(st + G2A + row * GP + seg * 16,
                           B + (size_t)(n0 + row) * 128 + kc + seg * 8);
            }
        }
        asm volatile("cp.async.commit_group;");
    }
    if (tid < 64) sBias[tid] = bias[n0 + tid];

    float acc[2][4][4];
    #pragma unroll
    for (int a1 = 0; a1 < 2; a1++)
        #pragma unroll
        for (int a2 = 0; a2 < 4; a2++)
            #pragma unroll
            for (int a3 = 0; a3 < 4; a3++) acc[a1][a2][a3] = 0.f;

    #pragma unroll
    for (int ch = 0; ch < 2; ch++) {
        if (ch == 0) asm volatile("cp.async.wait_group 1;");
        else         asm volatile("cp.async.wait_group 0;");
        __syncthreads();
        uint32_t st = sb + SM_FIX + ch * G2STAGE;
        #pragma unroll
        for (int ks = 0; ks < 4; ks++) {
            uint32_t ah[2][4];
            #pragma unroll
            for (int mt = 0; mt < 2; mt++) {
                uint32_t aoff = (uint32_t)((wm*32 + mt*16 + (lane & 15)) * GP + ks*32 + (lane >> 4) * 16);
                ldsm4(ah[mt], st + aoff);
            }
            #pragma unroll
            for (int nb = 0; nb < 2; nb++) {
                uint32_t boff = (uint32_t)((wn*32 + nb*16 + (lane & 15)) * GP + ks*32 + (lane >> 4) * 16);
                uint32_t bh[4];
                ldsm4(bh, st + G2A + boff);
                #pragma unroll
                for (int mt = 0; mt < 2; mt++) {
                    mma16816(acc[mt][2*nb],   ah[mt], bh[0], bh[2]);
                    mma16816(acc[mt][2*nb+1], ah[mt], bh[1], bh[3]);
                }
            }
        }
    }

    #pragma unroll
    for (int mt = 0; mt < 2; mt++) {
        int r0 = m0 + wm*32 + mt*16 + hrow;
        int pr0 = g_map[r0], pr1 = g_map[r0 + 8];
        #pragma unroll
        for (int j = 0; j < 4; j++) {
            int col = wn*32 + j*8 + q*2;
            float b0 = sBias[col], b1 = sBias[col+1];
            packh2(acc[mt][j][0] + b0, acc[mt][j][1] + b1, Ch, (size_t)pr0 * N + n0 + col);
            packh2(acc[mt][j][2] + b0, acc[mt][j][3] + b1, Ch, (size_t)pr1 * N + n0 + col);
        }
    }
}

// ================= fused FFN (compact rows) =====================================
__global__ void __launch_bounds__(256, 2) ffn_fused(
        const fp16* __restrict__ X, const fp16* __restrict__ W1,
        const fp16* __restrict__ W2,
        const float* __restrict__ b1, const float* __restrict__ b2,
        const float* __restrict__ lng, const float* __restrict__ lnb,
        float* __restrict__ Cf, fp16* __restrict__ Ch,
        int use_nrows, int M) {
    int m0 = blockIdx.y * 128;
    if (use_nrows && m0 >= g_nrows) return;
    char* sm = dyn_smem;
    uint32_t sb = smem_u32(sm);
    float* sB1 = (float*)sm;
    float* sB2 = (float*)(sm + 2048);
    float* sG  = (float*)(sm + 2560);
    float* sBt = (float*)(sm + 3072);
    float* sred = (float*)(sm + F2_W1);
    int tid = threadIdx.x, lane = tid & 31, wid = tid >> 5;
    int q = lane & 3, hrow = lane >> 2;
    int wm = wid & 3, wn = wid >> 2;

    #pragma unroll
    for (int t = 0; t < 8; t++) {
        int idx = tid + t * 256;
        int row = idx >> 4, seg = idx & 15;
        int c = seg >> 3, s2 = seg & 7;
        cp_async16(sb + F2_X + c * 18432 + row * GP + s2 * 16,
                   X + (size_t)(m0 + row) * 128 + c * 64 + s2 * 8);
    }
    #pragma unroll
    for (int t = 0; t < 4; t++) {
        int idx = tid + t * 256;
        int row = idx >> 4, seg = idx & 15;
        int c = seg >> 3, s2 = seg & 7;
        cp_async16(sb + F2_W1 + c * 9216 + row * GP + s2 * 16,
                   W1 + (size_t)row * 128 + c * 64 + s2 * 8);
    }
    #pragma unroll
    for (int t = 0; t < 4; t++) {
        int idx = tid + t * 256;
        int row = idx >> 3, seg = idx & 7;
        cp_async16(sb + F2_W2 + row * GP + seg * 16,
                   W2 + (size_t)row * 512 + seg * 8);
    }
    asm volatile("cp.async.commit_group;");

    if (tid < 128) { sB2[tid] = b2[tid]; sG[tid] = lng[tid]; sBt[tid] = lnb[tid]; }
    for (int i = tid; i < 512; i += 256) sB1[i] = b1[i];

    float acc[2][8][4];
    #pragma unroll
    for (int a1 = 0; a1 < 2; a1++)
        #pragma unroll
        for (int a2 = 0; a2 < 8; a2++)
            #pragma unroll
            for (int a3 = 0; a3 < 4; a3++) acc[a1][a2][a3] = 0.f;

    for (int f = 0; f < 8; f++) {
        asm volatile("cp.async.wait_group 0;");
        __syncthreads();
        float acc1[2][4][4];
        #pragma unroll
        for (int a1 = 0; a1 < 2; a1++)
            #pragma unroll
            for (int a2 = 0; a2 < 4; a2++)
                #pragma unroll
                for (int a3 = 0; a3 < 4; a3++) acc1[a1][a2][a3] = 0.f;
        #pragma unroll
        for (int kc = 0; kc < 2; kc++) {
            uint32_t aX = sb + F2_X + kc * 18432;
            uint32_t aW = sb + F2_W1 + kc * 9216;
            #pragma unroll
            for (int ks = 0; ks < 4; ks++) {
                uint32_t ah[2][4];
                #pragma unroll
                for (int mt = 0; mt < 2; mt++) {
                    uint32_t aoff = (uint32_t)((wm*32 + mt*16 + (lane & 15)) * GP + ks*32 + (lane >> 4) * 16);
                    ldsm4(ah[mt], aX + aoff);
                }
                #pragma unroll
                for (int nb = 0; nb < 2; nb++) {
                    uint32_t boff = (uint32_t)((wn*32 + nb*16 + (lane & 15)) * GP + ks*32 + (lane >> 4) * 16);
                    uint32_t bh[4];
                    ldsm4(bh, aW + boff);
                    #pragma unroll
                    for (int mt = 0; mt < 2; mt++) {
                        mma16816(acc1[mt][2*nb],   ah[mt], bh[0], bh[2]);
                        mma16816(acc1[mt][2*nb+1], ah[mt], bh[1], bh[3]);
                    }
                }
            }
        }
        #pragma unroll
        for (int mt = 0; mt < 2; mt++) {
            int r0 = wm*32 + mt*16 + hrow;
            #pragma unroll
            for (int j = 0; j < 4; j++) {
                int col = wn*32 + j*8 + q*2;
                float bb0 = sB1[f*64 + col], bb1 = sB1[f*64 + col + 1];
                float v0 = acc1[mt][j][0] + bb0, v1 = acc1[mt][j][1] + bb1;
                float v2 = acc1[mt][j][2] + bb0, v3 = acc1[mt][j][3] + bb1;
                v0 = 0.5f * v0 * (1.f + erff(v0 * 0.70710678118654752f));
                v1 = 0.5f * v1 * (1.f + erff(v1 * 0.70710678118654752f));
                v2 = 0.5f * v2 * (1.f + erff(v2 * 0.70710678118654752f));
                v3 = 0.5f * v3 * (1.f + erff(v3 * 0.70710678118654752f));
                *(__half2*)(sm + F2_HF + r0 * GP + col * 2)       = __floats2half2_rn(v0, v1);
                *(__half2*)(sm + F2_HF + (r0 + 8) * GP + col * 2) = __floats2half2_rn(v2, v3);
            }
        }
        __syncthreads();
        if (f + 1 < 8) {
            const fp16* W1n = W1 + (size_t)(f + 1) * 64 * 128;
            #pragma unroll
            for (int t = 0; t < 4; t++) {
                int idx = tid + t * 256;
                int row = idx >> 4, seg = idx & 15;
                int c = seg >> 3, s2 = seg & 7;
                cp_async16(sb + F2_W1 + c * 9216 + row * GP + s2 * 16,
                           W1n + (size_t)row * 128 + c * 64 + s2 * 8);
            }
        }
        asm volatile("cp.async.commit_group;");
        #pragma unroll
        for (int ks = 0; ks < 4; ks++) {
            uint32_t ah[2][4];
            #pragma unroll
            for (int mt = 0; mt < 2; mt++) {
                uint32_t aoff = (uint32_t)((wm*32 + mt*16 + (lane & 15)) * GP + ks*32 + (lane >> 4) * 16);
                ldsm4(ah[mt], sb + F2_HF + aoff);
            }
            #pragma unroll
            for (int nb = 0; nb < 4; nb++) {
                uint32_t boff = (uint32_t)((wn*64 + nb*16 + (lane & 15)) * GP + ks*32 + (lane >> 4) * 16);
                uint32_t bh[4];
                ldsm4(bh, sb + F2_W2 + boff);
                #pragma unroll
                for (int mt = 0; mt < 2; mt++) {
                    mma16816(acc[mt][2*nb],   ah[mt], bh[0], bh[2]);
                    mma16816(acc[mt][2*nb+1], ah[mt], bh[1], bh[3]);
                }
            }
        }
        __syncthreads();
        if (f + 1 < 8) {
            const fp16* W2n = W2 + (size_t)(f + 1) * 64;
            #pragma unroll
            for (int t = 0; t < 4; t++) {
                int idx = tid + t * 256;
                int row = idx >> 3, seg = idx & 7;
                cp_async16(sb + F2_W2 + row * GP + seg * 16,
                           W2n + (size_t)row * 512 + seg * 8);
            }
        }
        asm volatile("cp.async.commit_group;");
    }

    float mu[2][2], rs[2][2];
    #pragma unroll
    for (int mt = 0; mt < 2; mt++) {
        int rl = wm*32 + mt*16 + hrow;
        #pragma unroll
        for (int j = 0; j < 8; j++) {
            int col = wn*64 + j*8 + q*2;
            float b0 = sB2[col], b1v = sB2[col+1];
            uint32_t xoff = (uint32_t)(F2_X + wn * 18432 + (j*8 + q*2) * 2);
            float2 ra = __half22float2(*(const __half2*)(sm + xoff + rl * GP));
            float2 rb = __half22float2(*(const __half2*)(sm + xoff + (rl + 8) * GP));
            acc[mt][j][0] += b0 + ra.x;  acc[mt][j][1] += b1v + ra.y;
            acc[mt][j][2] += b0 + rb.x;  acc[mt][j][3] += b1v + rb.y;
        }
    }
    float ssum[2][2] = {{0,0},{0,0}}, ssq[2][2] = {{0,0},{0,0}};
    #pragma unroll
    for (int mt = 0; mt < 2; mt++)
        #pragma unroll
        for (int j = 0; j < 8; j++)
            #pragma unroll
            for (int hh = 0; hh < 2; hh++) {
                float v0 = acc[mt][j][2*hh], v1 = acc[mt][j][2*hh+1];
                ssum[mt][hh] += v0 + v1;
                ssq[mt][hh]  += v0*v0 + v1*v1;
            }
    #pragma unroll
    for (int mt = 0; mt < 2; mt++)
        #pragma unroll
        for (int hh = 0; hh < 2; hh++) {
            ssum[mt][hh] += __shfl_xor_sync(0xffffffffu, ssum[mt][hh], 1);
            ssum[mt][hh] += __shfl_xor_sync(0xffffffffu, ssum[mt][hh], 2);
            ssq[mt][hh]  += __shfl_xor_sync(0xffffffffu, ssq[mt][hh], 1);
            ssq[mt][hh]  += __shfl_xor_sync(0xffffffffu, ssq[mt][hh], 2);
        }
    if (q == 0) {
        #pragma unroll
        for (int mt = 0; mt < 2; mt++)
            #pragma unroll
            for (int hh = 0; hh < 2; hh++) {
                int lr = wm*32 + mt*16 + hrow + hh*8;
                sred[lr*2 + wn]       = ssum[mt][hh];
                sred[256 + lr*2 + wn] = ssq[mt][hh];
            }
    }
    __syncthreads();
    #pragma unroll
    for (int mt = 0; mt < 2; mt++)
        #pragma unroll
        for (int hh = 0; hh < 2; hh++) {
            int lr = wm*32 + mt*16 + hrow + hh*8;
            float S  = sred[lr*2] + sred[lr*2 + 1];
            float S2 = sred[256 + lr*2] + sred[256 + lr*2 + 1];
            float m  = S * (1.f/128.f);
            float var = S2 * (1.f/128.f) - m * m;
            mu[mt][hh] = m;
            rs[mt][hh] = rsqrtf(var + 1e-5f);
        }
    #pragma unroll
    for (int mt = 0; mt < 2; mt++) {
        int r0 = m0 + wm*32 + mt*16 + hrow;
        #pragma unroll
        for (int j = 0; j < 8; j++) {
            int col = wn*64 + j*8 + q*2;
            float g0 = sG[col], g1 = sG[col+1], bb0 = sBt[col], bb1 = sBt[col+1];
            float v0 = (acc[mt][j][0] - mu[mt][0]) * rs[mt][0] * g0 + bb0;
            float v1 = (acc[mt][j][1] - mu[mt][0]) * rs[mt][0] * g1 + bb1;
            float v2 = (acc[mt][j][2] - mu[mt][1]) * rs[mt][1] * g0 + bb0;
            float v3 = (acc[mt][j][3] - mu[mt][1]) * rs[mt][1] * g1 + bb1;
            if (Cf) {
                *(float2*)(Cf + (size_t)r0 * 128 + col)     = make_float2(v0, v1);
                *(float2*)(Cf + (size_t)(r0+8) * 128 + col) = make_float2(v2, v3);
            }
            if (Ch) {
                packh2(v0, v1, Ch, (size_t)r0 * 128 + col);
                packh2(v2, v3, Ch, (size_t)(r0+8) * 128 + col);
            }
        }
    }
}

// ======= out-projection GEMM (K=512): gathered A rows via map, compact out ======
__global__ void __launch_bounds__(256, 2) hmma_gemm_out(
        const fp16* __restrict__ A, const fp16* __restrict__ B,
        const float* __restrict__ bias, const fp16* __restrict__ Res,
        const float* __restrict__ lng, const float* __restrict__ lnb,
        fp16* __restrict__ Ch, int use_map, int M) {
    int m0 = blockIdx.y * 128;
    if (use_map && m0 >= g_nrows) return;

    char* sm = dyn_smem;
    float* sBias = (float*)sm;
    float* sG    = sBias + 128;
    float* sB    = sG + 128;
    float* sred  = (float*)(sm + SM_FIX);
    uint32_t sb = smem_u32(sm);

    int tid = threadIdx.x, lane = tid & 31, wid = tid >> 5;
    int q = lane & 3, hrow = lane >> 2;
    int wm = wid & 3, wn = wid >> 2;
    int n0 = blockIdx.x * 128;

    // precompute gathered A row bases
    int browA = tid >> 3, segA = tid & 7;
    size_t prA[4];
    #pragma unroll
    for (int t = 0; t < 4; t++) {
        int r = m0 + browA + t * 32;
        int pr = use_map ? g_map[r] : r;
        prA[t] = (size_t)pr * 512;
    }

    if (tid < 128) {
        sBias[tid] = bias[n0 + tid];
        sG[tid] = lng[n0 + tid]; sB[tid] = lnb[n0 + tid];
    }

    float acc[2][8][4];
    #pragma unroll
    for (int a1 = 0; a1 < 2; a1++)
        #pragma unroll
        for (int a2 = 0; a2 < 8; a2++)
            #pragma unroll
            for (int a3 = 0; a3 < 4; a3++) acc[a1][a2][a3] = 0.f;

    #define LOADCHUNK(st, kc) { \
        _Pragma("unroll") \
        for (int t = 0; t < 4; t++) { \
            uint32_t so = (browA + t*32) * GP + segA * 16; \
            cp_async16((st) + so,         A + prA[t] + (kc) + segA * 8); \
            cp_async16((st) + GTILE + so, B + (size_t)(n0 + browA + t*32) * 512 + (kc) + segA * 8); \
        } }

    LOADCHUNK(sb + SM_FIX, 0);
    asm volatile("cp.async.commit_group;");
    LOADCHUNK(sb + SM_FIX + GSTAGE, 64);
    asm volatile("cp.async.commit_group;");

    for (int ch = 0; ch < 8; ch++) {
        asm volatile("cp.async.wait_group 1;");
        __syncthreads();
        uint32_t st = sb + SM_FIX + (ch % NSTAGE) * GSTAGE;
        uint32_t aA = st, aB = st + GTILE;
        #pragma unroll
        for (int ks = 0; ks < 4; ks++) {
            uint32_t ah[2][4];
            #pragma unroll
            for (int mt = 0; mt < 2; mt++) {
                uint32_t aoff = (uint32_t)((wm*32 + mt*16 + (lane & 15)) * GP + ks*32 + (lane >> 4) * 16);
                ldsm4(ah[mt], aA + aoff);
            }
            #pragma unroll
            for (int nb = 0; nb < 4; nb++) {
                uint32_t boff = (uint32_t)((wn*64 + nb*16 + (lane & 15)) * GP + ks*32 + (lane >> 4) * 16);
                uint32_t bh[4];
                ldsm4(bh, aB + boff);
                #pragma unroll
                for (int mt = 0; mt < 2; mt++) {
                    mma16816(acc[mt][2*nb],   ah[mt], bh[0], bh[2]);
                    mma16816(acc[mt][2*nb+1], ah[mt], bh[1], bh[3]);
                }
            }
        }
        if (ch + 2 < 8) {
            uint32_t st2 = sb + SM_FIX + ((ch + 2) % NSTAGE) * GSTAGE;
            int kc2 = (ch + 2) << 6;
            LOADCHUNK(st2, kc2);
        }
        asm volatile("cp.async.commit_group;");
    }
    __syncthreads();

    // epilogue: bias + residual + LN -> fp16 compact out
    float mu[2][2], rs[2][2];
    #pragma unroll
    for (int mt = 0; mt < 2; mt++) {
        int r0 = m0 + wm*32 + mt*16 + hrow;
        #pragma unroll
        for (int j = 0; j < 8; j++) {
            int col = wn*64 + j*8 + q*2;
            float b0 = sBias[col], b1 = sBias[col+1];
            float2 ra = __half22float2(*(const __half2*)(Res + (size_t)r0 * 128 + col));
            float2 rb = __half22float2(*(const __half2*)(Res + (size_t)(r0+8) * 128 + col));
            acc[mt][j][0] += b0 + ra.x; acc[mt][j][1] += b1 + ra.y;
            acc[mt][j][2] += b0 + rb.x; acc[mt][j][3] += b1 + rb.y;
        }
    }
    float ssum[2][2] = {{0,0},{0,0}}, ssq[2][2] = {{0,0},{0,0}};
    #pragma unroll
    for (int mt = 0; mt < 2; mt++)
        #pragma unroll
        for (int j = 0; j < 8; j++)
            #pragma unroll
            for (int hh = 0; hh < 2; hh++) {
                float v0 = acc[mt][j][2*hh], v1 = acc[mt][j][2*hh+1];
                ssum[mt][hh] += v0 + v1;
                ssq[mt][hh]  += v0*v0 + v1*v1;
            }
    #pragma unroll
    for (int mt = 0; mt < 2; mt++)
        #pragma unroll
        for (int hh = 0; hh < 2; hh++) {
            ssum[mt][hh] += __shfl_xor_sync(0xffffffffu, ssum[mt][hh], 1);
            ssum[mt][hh] += __shfl_xor_sync(0xffffffffu, ssum[mt][hh], 2);
            ssq[mt][hh]  += __shfl_xor_sync(0xffffffffu, ssq[mt][hh], 1);
            ssq[mt][hh]  += __shfl_xor_sync(0xffffffffu, ssq[mt][hh], 2);
        }
    if (q == 0) {
        #pragma unroll
        for (int mt = 0; mt < 2; mt++)
            #pragma unroll
            for (int hh = 0; hh < 2; hh++) {
                int lr = wm*32 + mt*16 + hrow + hh*8;
                sred[lr*2 + wn]       = ssum[mt][hh];
                sred[256 + lr*2 + wn] = ssq[mt][hh];
            }
    }
    __syncthreads();
    #pragma unroll
    for (int mt = 0; mt < 2; mt++)
        #pragma unroll
        for (int hh = 0; hh < 2; hh++) {
            int lr = wm*32 + mt*16 + hrow + hh*8;
            float S  = sred[lr*2] + sred[lr*2 + 1];
            float S2 = sred[256 + lr*2] + sred[256 + lr*2 + 1];
            float m  = S * (1.f/128.f);
            float var = S2 * (1.f/128.f) - m * m;
            mu[mt][hh] = m;
            rs[mt][hh] = rsqrtf(var + 1e-5f);
        }
    #pragma unroll
    for (int mt = 0; mt < 2; mt++) {
        int r0 = m0 + wm*32 + mt*16 + hrow;
        #pragma unroll
        for (int j = 0; j < 8; j++) {
            int col = wn*64 + j*8 + q*2;
            float g0 = sG[col], g1 = sG[col+1], bb0 = sB[col], bb1 = sB[col+1];
            float v0 = (acc[mt][j][0] - mu[mt][0]) * rs[mt][0] * g0 + bb0;
            float v1 = (acc[mt][j][1] - mu[mt][0]) * rs[mt][0] * g1 + bb1;
            float v2 = (acc[mt][j][2] - mu[mt][1]) * rs[mt][1] * g0 + bb0;
            float v3 = (acc[mt][j][3] - mu[mt][1]) * rs[mt][1] * g1 + bb1;
            packh2(v0, v1, Ch, (size_t)r0 * 128 + col);
            packh2(v2, v3, Ch, (size_t)(r0+8) * 128 + col);
        }
    }
}

// ---------------- host driver ---------------------------------------------------
extern "C" void kernel_launch(void* const* d_in, const int* in_sizes, int n_in,
                              void* d_out, int out_size) {
    const float* token_emb  = (const float*)d_in[0];
    const float* emb_ln_g   = (const float*)d_in[1];
    const float* emb_ln_b   = (const float*)d_in[2];
    const float* params_log = (const float*)d_in[3];
    const float* in_wr      = (const float*)d_in[4];
    const float* in_wi      = (const float*)d_in[5];
    const float* in_br      = (const float*)d_in[6];
    const float* in_bi      = (const float*)d_in[7];
    const float* out_wr     = (const float*)d_in[8];
    const float* out_wi     = (const float*)d_in[9];
    const float* out_br     = (const float*)d_in[10];
    const float* lru_ln_g   = (const float*)d_in[12];
    const float* lru_ln_b   = (const float*)d_in[13];
    const float* w1         = (const float*)d_in[14];
    const float* b1         = (const float*)d_in[15];
    const float* w2         = (const float*)d_in[16];
    const float* b2         = (const float*)d_in[17];
    const float* ffn_ln_g   = (const float*)d_in[18];
    const float* ffn_ln_b   = (const float*)d_in[19];
    const int*   item_seq   = (const int*)d_in[20];
    const int*   item_len   = (const int*)d_in[21];
    float* out = (float*)d_out;

    float *pbin;
    fp16 *pxc, *px2c, *phh, *pWin, *pWout, *pw1, *pw2;
    fp16 *psm1h, *phgh, *pxgh;
    cudaGetSymbolAddress((void**)&pxc,   g_xc);
    cudaGetSymbolAddress((void**)&px2c,  g_x2c);
    cudaGetSymbolAddress((void**)&phh,   g_hh);
    cudaGetSymbolAddress((void**)&pWin,  g_Win);
    cudaGetSymbolAddress((void**)&pbin,  g_bin);
    cudaGetSymbolAddress((void**)&pWout, g_Wout);
    cudaGetSymbolAddress((void**)&pw1,   g_w1);
    cudaGetSymbolAddress((void**)&pw2,   g_w2);
    cudaGetSymbolAddress((void**)&pxgh,  g_xgh);
    cudaGetSymbolAddress((void**)&psm1h, g_sm1h);
    cudaGetSymbolAddress((void**)&phgh,  g_hgh);

    cudaFuncSetAttribute(hmma_gemm_out, cudaFuncAttributeMaxDynamicSharedMemorySize, GSM_TOT);
    cudaFuncSetAttribute(hmma_gemm64, cudaFuncAttributeMaxDynamicSharedMemorySize, G2SM);
    cudaFuncSetAttribute(ffn_fused, cudaFuncAttributeMaxDynamicSharedMemorySize, F2_SM);

    prefix_kernel<<<1, 512>>>(item_len);
    maptail_kernel<<<MAXR/256, 256>>>();
    for (int li = 0; li < NLAY; li++) {
        pack_kernel<<<1024, 256>>>(in_wr, in_wi, in_br, in_bi, out_wr, out_wi,
                                   w1, w2, params_log, li);
        lam_kernel<<<128, 256>>>(params_log, li);
    }
    embed_kernel<<<MAXR/8, 256>>>(token_emb, emb_ln_g, emb_ln_b, item_seq, item_len, pxc);

    for (int li = 0; li < NLAY; li++) {
        // in-projection on compact rows, scatter h to padded layout
        hmma_gemm64<<<dim3(8, MAXT), 256, G2SM>>>(
            pxc, pWin + (size_t)li * 2*DH*DD, pbin + li * 2*DH, phh, 512);
        scan_kernel<<<dim3(8, BB), 256>>>(phh, item_seq, item_len, li);

        if (li == 0) {
            hmma_gemm_out<<<dim3(1, MAXT), 256, GSM_TOT>>>(
                phh, pWout + (size_t)li * DD*2*DH, out_br + li*DD, pxc,
                lru_ln_g + li*DD, lru_ln_b + li*DD, px2c, 1, MAXR);
            ffn_fused<<<dim3(1, MAXT), 256, F2_SM>>>(
                px2c, pw1 + (size_t)li * DFF*DD, pw2 + (size_t)li * DD*DFF,
                b1 + li*DFF, b2 + li*DD, ffn_ln_g + li*DD, ffn_ln_b + li*DD,
                nullptr, pxc, 1, MAXR);
        } else {
            gather_kernel<<<BB, 512>>>(phh, pxc, item_len, phgh, pxgh);
            hmma_gemm_out<<<dim3(1, BB/128), 256, GSM_TOT>>>(
                phgh, pWout + (size_t)li * DD*2*DH, out_br + li*DD, pxgh,
                lru_ln_g + li*DD, lru_ln_b + li*DD, psm1h, 0, BB);
            ffn_fused<<<dim3(1, BB/128), 256, F2_SM>>>(
                psm1h, pw1 + (size_t)li * DFF*DD, pw2 + (size_t)li * DD*DFF,
                b1 + li*DFF, b2 + li*DD, ffn_ln_g + li*DD, ffn_ln_b + li*DD,
                out, nullptr, 0, BB);
        }
    }
}